// round 3
// baseline (speedup 1.0000x reference)
#include <cuda_runtime.h>
#include <math.h>

#define NE 160000
#define NN 10000
#define N64 (NN*64)

#define S3f  1.7320508075688772f
#define S5f  2.2360679774997896f
#define S15f 3.8729833462074170f
#define PIf  3.14159265358979323846f
#define K0C  (0.0625f)
#define K1C  (0.0625f/S3f)
#define K2C  (0.0625f/S5f)
#define K4N  (-0.0625f/S3f)
#define K9N  (0.0625f/S5f)

// ---------------- scratch ----------------
__device__ float d_vec[NE*3];
__device__ float d_r[NE];
__device__ float d_Y[NE*8];
__device__ float d_feat[NE*8];
__device__ float d_gfeat[NE*8];
__device__ float d_gY[NE*8];
__device__ float d_z0a[NE*64], d_z0b[NE*64], d_z0c[NE*64];
__device__ float d_z1a[NE*64], d_z1b[NE*64], d_z1c[NE*64];
__device__ float d_R0[NE*192];   // reused in-place as gR0
__device__ float d_R1[NE*192];   // reused in-place as gR1

__device__ int   d_sp[NN];
__device__ float d_hup0[N64];
__device__ float d_h1_0[N64];
__device__ float d_hup1_0[N64];
__device__ float d_hup1_1[NN*192];
__device__ float d_hup1_2[NN*320];
__device__ float d_agg0_0[N64];
__device__ float d_agg0_1[NN*192];
__device__ float d_agg0_2[NN*320];
__device__ float d_agg1[3*N64];
__device__ float d_gagg1[3*N64];
__device__ float d_gh1_0[N64];
__device__ float d_gHup1_0[N64];
__device__ float d_gHup1_1[NN*192];
__device__ float d_gHup1_2[NN*320];
__device__ float d_gagg0_0[N64];
__device__ float d_gagg0_1[NN*192];
__device__ float d_gagg0_2[NN*320];
__device__ float d_W01[4096], d_W02[4096];
__device__ float d_W2T[2*4096], d_W3T[2*4096], d_W4T[2*12288];
__device__ float d_e[48];

__device__ __forceinline__ float siluf(float x){ float s=1.f/(1.f+expf(-x)); return x*s; }
__device__ __forceinline__ float dsiluf(float x){ float s=1.f/(1.f+expf(-x)); return s*(1.f+x*(1.f-s)); }

// ----------------------------------------------------------------------------
__global__ void k_zero(float* __restrict__ out){
    long i = (long)blockIdx.x*blockDim.x + threadIdx.x;
    long st = (long)gridDim.x*blockDim.x;
    for (long j=i;j<48;j+=st) d_e[j]=0.f;
    for (long j=i;j<N64;j+=st){ d_agg0_0[j]=0.f; d_gHup1_0[j]=0.f; }
    for (long j=i;j<(long)NN*192;j+=st){ d_agg0_1[j]=0.f; d_gHup1_1[j]=0.f; }
    for (long j=i;j<(long)NN*320;j+=st){ d_agg0_2[j]=0.f; d_gHup1_2[j]=0.f; }
    for (long j=i;j<3*(long)N64;j+=st) d_agg1[j]=0.f;
    for (long j=i;j<30064;j+=st) out[j]=0.f;
}

// ----------------------------------------------------------------------------
__global__ void k_transpose(const float* __restrict__ w2a,const float* __restrict__ w3a,
                            const float* __restrict__ w4a,const float* __restrict__ w2b,
                            const float* __restrict__ w3b,const float* __restrict__ w4b){
    int i = blockIdx.x*blockDim.x + threadIdx.x;
    if (i < 4096){
        int k=i>>6, j=i&63;
        d_W2T[i]      = w2a[j*64+k];
        d_W3T[i]      = w3a[j*64+k];
        d_W2T[4096+i] = w2b[j*64+k];
        d_W3T[4096+i] = w3b[j*64+k];
    }
    if (i < 12288){
        int p=i>>12, rem=i&4095, c=rem>>6, j=rem&63;
        const int colA[3]={0,64,128}, colB[3]={0,256,576};
        d_W4T[i]       = w4a[j*192 + colA[p] + c];
        d_W4T[12288+i] = w4b[j*832 + colB[p] + c];
    }
}

// ----------------------------------------------------------------------------
__global__ void k_precW(const float* __restrict__ w_out0, const float* __restrict__ w_up1){
    int c = blockIdx.x, l = blockIdx.y+1, d2 = threadIdx.x;
    const float* wo = w_out0 + l*4096;
    const float* wu = w_up1  + l*4096;
    float a=0.f;
    for (int d=0;d<64;d++) a = fmaf(wo[c*64+d], wu[d*64+d2], a);
    if (l==1) d_W01[c*64+d2]=a; else d_W02[c*64+d2]=a;
}

// ----------------------------------------------------------------------------
__global__ void k_edge_geom(const float* __restrict__ pos, const float* __restrict__ shifts,
                            const int* __restrict__ ei){
    int e = blockIdx.x*blockDim.x + threadIdx.x;
    if (e >= NE) return;
    int s = ei[e], t = ei[NE+e];
    float vx = pos[t*3+0]-pos[s*3+0]+shifts[e*3+0];
    float vy = pos[t*3+1]-pos[s*3+1]+shifts[e*3+1];
    float vz = pos[t*3+2]-pos[s*3+2]+shifts[e*3+2];
    float r  = sqrtf(vx*vx+vy*vy+vz*vz + 1e-12f);
    d_vec[e*3+0]=vx; d_vec[e*3+1]=vy; d_vec[e*3+2]=vz; d_r[e]=r;
    float inv = 1.0f/r;
    float x=vx*inv, y=vy*inv, z=vz*inv;
    d_Y[e*8+0]=S3f*y;  d_Y[e*8+1]=S3f*z;  d_Y[e*8+2]=S3f*x;
    d_Y[e*8+3]=S15f*x*y; d_Y[e*8+4]=S15f*y*z;
    d_Y[e*8+5]=0.5f*S5f*(3.f*z*z-1.f);
    d_Y[e*8+6]=S15f*x*z; d_Y[e*8+7]=0.5f*S15f*(x*x-y*y);
    float uu = r*0.2f, fc = 0.f;
    if (uu < 1.0f){
        float u2=uu*uu, u4=u2*u2, u5=u4*uu, u6=u5*uu, u7=u6*uu;
        fc = 1.f - 21.f*u5 + 35.f*u6 - 15.f*u7;
    }
    float c0 = sqrtf(0.4f);
    #pragma unroll
    for (int q=1;q<=8;q++){
        float a = (float)q*(PIf/5.0f);
        d_feat[e*8+q-1] = c0*sinf(a*r)*inv*fc;
    }
}

// ----------------------------------------------------------------------------
__global__ void k_mlp_fwd(const float* __restrict__ w1, const float* __restrict__ w2,
                          const float* __restrict__ w3, const float* __restrict__ w4,
                          int w4s, int cb1, int cb2, int which){
    __shared__ float sf[8][8];
    __shared__ float st[8][64];
    int j = threadIdx.x, ry = threadIdx.y;
    int e = blockIdx.x*8 + ry;
    float* za = which ? d_z1a : d_z0a;
    float* zb = which ? d_z1b : d_z0b;
    float* zc = which ? d_z1c : d_z0c;
    float* Ro = which ? d_R1  : d_R0;
    if (j < 8) sf[ry][j] = d_feat[e*8+j];
    __syncthreads();
    float z = 0.f;
    #pragma unroll
    for (int i=0;i<8;i++) z = fmaf(sf[ry][i], w1[i*64+j], z);
    za[e*64+j]=z;
    st[ry][j]=siluf(z);
    __syncthreads();
    z=0.f;
    for (int k=0;k<64;k++) z = fmaf(st[ry][k], w2[k*64+j], z);
    zb[e*64+j]=z;
    __syncthreads();
    st[ry][j]=siluf(z);
    __syncthreads();
    z=0.f;
    for (int k=0;k<64;k++) z = fmaf(st[ry][k], w3[k*64+j], z);
    zc[e*64+j]=z;
    __syncthreads();
    st[ry][j]=siluf(z);
    __syncthreads();
    float a0=0.f,a1=0.f,a2=0.f;
    for (int k=0;k<64;k++){
        float tv = st[ry][k];
        const float* wr = w4 + k*w4s + j;
        a0 = fmaf(tv, wr[0],   a0);
        a1 = fmaf(tv, wr[cb1], a1);
        a2 = fmaf(tv, wr[cb2], a2);
    }
    Ro[e*192      + j] = a0;
    Ro[e*192 + 64 + j] = a1;
    Ro[e*192 +128 + j] = a2;
}

// ----------------------------------------------------------------------------
__global__ void k_mlp_bwd(const float* __restrict__ w1, int which, int acc){
    __shared__ float sgr[8][192];
    __shared__ float sg[8][64];
    int j = threadIdx.x, ry = threadIdx.y;
    int e = blockIdx.x*8 + ry;
    const float* za = which ? d_z1a : d_z0a;
    const float* zb = which ? d_z1b : d_z0b;
    const float* zc = which ? d_z1c : d_z0c;
    const float* gR = which ? d_R1  : d_R0;
    const float* W2T = d_W2T + which*4096;
    const float* W3T = d_W3T + which*4096;
    const float* W4T = d_W4T + which*12288;
    for (int i=j;i<192;i+=64) sgr[ry][i] = gR[e*192+i];
    __syncthreads();
    float g=0.f;
    #pragma unroll
    for (int p=0;p<3;p++)
        for (int c=0;c<64;c++)
            g = fmaf(sgr[ry][p*64+c], W4T[p*4096 + c*64 + j], g);
    g *= dsiluf(zc[e*64+j]);
    sg[ry][j]=g;
    __syncthreads();
    float g2=0.f;
    for (int k=0;k<64;k++) g2 = fmaf(sg[ry][k], W3T[k*64+j], g2);
    g2 *= dsiluf(zb[e*64+j]);
    __syncthreads();
    sg[ry][j]=g2;
    __syncthreads();
    float g1=0.f;
    for (int k=0;k<64;k++) g1 = fmaf(sg[ry][k], W2T[k*64+j], g1);
    g1 *= dsiluf(za[e*64+j]);
    __syncthreads();
    sg[ry][j]=g1;
    __syncthreads();
    if (j < 8){
        float gf=0.f;
        for (int k=0;k<64;k++) gf = fmaf(sg[ry][k], w1[j*64+k], gf);
        if (acc) d_gfeat[e*8+j] += gf; else d_gfeat[e*8+j] = gf;
    }
}

// ----------------------------------------------------------------------------
__global__ void k_node_init(const float* __restrict__ attrs, const float* __restrict__ w_emb,
                            const float* __restrict__ w_up0, const float* __restrict__ aener,
                            const int* __restrict__ batch){
    int n = blockIdx.x, c = threadIdx.x;
    __shared__ int ssp;
    __shared__ float sh0[64];
    if (c==0){
        int sp=0;
        for (int q=0;q<10;q++) if (attrs[n*10+q] > 0.5f) sp=q;
        ssp=sp; d_sp[n]=sp;
        atomicAdd(&d_e[batch[n]], aener[sp]);
    }
    __syncthreads();
    sh0[c]=w_emb[ssp*64+c];
    __syncthreads();
    float a=0.f;
    for (int k=0;k<64;k++) a = fmaf(sh0[k], w_up0[k*64+c], a);
    d_hup0[n*64+c]=a;
}

// ----------------------------------------------------------------------------
__global__ void k_int0_edge(const int* __restrict__ ei){
    int idx = blockIdx.x*blockDim.x + threadIdx.x;
    int e = idx>>6, c = idx&63;
    int s = ei[e], t = ei[NE+e];
    float hup = d_hup0[s*64+c];
    const float* Rb = d_R0 + e*192;
    const float* Ye = d_Y + e*8;
    atomicAdd(&d_agg0_0[t*64+c], hup*Rb[c]*K0C);
    float m1 = hup*Rb[64+c]*K1C;
    float* a1 = d_agg0_1 + (t*64+c)*3;
    atomicAdd(a1+0, m1*Ye[0]); atomicAdd(a1+1, m1*Ye[1]); atomicAdd(a1+2, m1*Ye[2]);
    float m2 = hup*Rb[128+c]*K2C;
    float* a2 = d_agg0_2 + (t*64+c)*5;
    #pragma unroll
    for (int k=0;k<5;k++) atomicAdd(a2+k, m2*Ye[3+k]);
}

// ----------------------------------------------------------------------------
__global__ void k_int0_node(const float* __restrict__ w_emb, const float* __restrict__ w_out0,
                            const float* __restrict__ w_sc0, const float* __restrict__ w_r0,
                            const float* __restrict__ w_up1, const int* __restrict__ batch){
    int n=blockIdx.x, tx=threadIdx.x;
    __shared__ float sA0[64], sA1[192], sA2[320], sh0[64], sh1[64];
    __shared__ float sred[2];
    int sp = d_sp[n];
    sA0[tx]=d_agg0_0[n*64+tx];
    sh0[tx]=w_emb[sp*64+tx];
    for (int i=tx;i<192;i+=64) sA1[i]=d_agg0_1[n*192+i];
    for (int i=tx;i<320;i+=64) sA2[i]=d_agg0_2[n*320+i];
    __syncthreads();
    const float* wsc = w_sc0 + sp*4096;
    float acc=0.f;
    for (int c=0;c<64;c++){
        acc = fmaf(sA0[c], w_out0[c*64+tx], acc);
        acc = fmaf(sh0[c], wsc[c*64+tx], acc);
    }
    d_h1_0[n*64+tx]=acc;
    sh1[tx]=acc;
    float ev = acc*w_r0[tx];
    #pragma unroll
    for (int off=16;off>0;off>>=1) ev += __shfl_xor_sync(0xffffffffu, ev, off);
    if ((tx&31)==0) sred[tx>>5]=ev;
    __syncthreads();
    if (tx==0) atomicAdd(&d_e[16+batch[n]], sred[0]+sred[1]);
    float a=0.f;
    for (int c=0;c<64;c++) a = fmaf(sh1[c], w_up1[c*64+tx], a);
    d_hup1_0[n*64+tx]=a;
    float b0=0.f,b1=0.f,b2=0.f;
    for (int c=0;c<64;c++){
        float w = d_W01[c*64+tx];
        b0=fmaf(sA1[c*3+0],w,b0); b1=fmaf(sA1[c*3+1],w,b1); b2=fmaf(sA1[c*3+2],w,b2);
    }
    float* h1 = d_hup1_1 + (n*64+tx)*3;
    h1[0]=b0; h1[1]=b1; h1[2]=b2;
    float e0_=0.f,e1_=0.f,e2_=0.f,e3_=0.f,e4_=0.f;
    for (int c=0;c<64;c++){
        float w = d_W02[c*64+tx];
        e0_=fmaf(sA2[c*5+0],w,e0_); e1_=fmaf(sA2[c*5+1],w,e1_);
        e2_=fmaf(sA2[c*5+2],w,e2_); e3_=fmaf(sA2[c*5+3],w,e3_);
        e4_=fmaf(sA2[c*5+4],w,e4_);
    }
    float* h2 = d_hup1_2 + (n*64+tx)*5;
    h2[0]=e0_; h2[1]=e1_; h2[2]=e2_; h2[3]=e3_; h2[4]=e4_;
}

// ----------------------------------------------------------------------------
__global__ void k_int1_edge(const int* __restrict__ ei){
    int idx = blockIdx.x*blockDim.x + threadIdx.x;
    int e = idx>>6, c = idx&63;
    int s = ei[e], t = ei[NE+e];
    const float* Rb = d_R1 + e*192;
    const float* Ye = d_Y + e*8;
    atomicAdd(&d_agg1[t*64+c], d_hup1_0[s*64+c]*Rb[c]*K0C);
    const float* hv1 = d_hup1_1 + (s*64+c)*3;
    float S1 = Ye[0]*hv1[0]+Ye[1]*hv1[1]+Ye[2]*hv1[2];
    atomicAdd(&d_agg1[N64 + t*64+c], S1*Rb[64+c]*K4N);
    const float* hv2 = d_hup1_2 + (s*64+c)*5;
    float S2 = Ye[3]*hv2[0]+Ye[4]*hv2[1]+Ye[5]*hv2[2]+Ye[6]*hv2[3]+Ye[7]*hv2[4];
    atomicAdd(&d_agg1[2*N64 + t*64+c], S2*Rb[128+c]*K9N);
}

// ----------------------------------------------------------------------------
__global__ void k_int1_node(const float* __restrict__ w_out1, const float* __restrict__ w_sc1,
                            const float* __restrict__ w_m1, const float* __restrict__ w_m2,
                            const float* __restrict__ w_r0, const int* __restrict__ batch){
    int n=blockIdx.x, tx=threadIdx.x;
    __shared__ float sA0[64], sA1[64], sA2[64], sh1[64], sh2[64], sg2[64];
    __shared__ float sv[16], sdz[16];
    int sp=d_sp[n];
    sA0[tx]=d_agg1[n*64+tx];
    sA1[tx]=d_agg1[N64+n*64+tx];
    sA2[tx]=d_agg1[2*N64+n*64+tx];
    sh1[tx]=d_h1_0[n*64+tx];
    __syncthreads();
    const float* wo0 = w_out1;
    const float* wo4 = w_out1 + 4*4096;
    const float* wo9 = w_out1 + 9*4096;
    const float* wsc = w_sc1 + sp*4096;   // w_sc1[0][sp]
    float h2=0.f;
    for (int c=0;c<64;c++){
        h2 = fmaf(sA0[c], wo0[c*64+tx], h2);
        h2 = fmaf(sA1[c], wo4[c*64+tx], h2);
        h2 = fmaf(sA2[c], wo9[c*64+tx], h2);
        h2 = fmaf(sh1[c], wsc[c*64+tx], h2);
    }
    sh2[tx]=h2;
    __syncthreads();
    if (tx < 16){
        float z=0.f;
        for (int d=0;d<64;d++) z = fmaf(sh2[d], w_m1[d*16+tx], z);
        float s=1.f/(1.f+expf(-z));
        sv[tx]  = z*s*w_m2[tx];
        sdz[tx] = s*(1.f+z*(1.f-s))*w_m2[tx];
    }
    __syncthreads();
    if (tx==0){
        float t=0.f;
        for (int q=0;q<16;q++) t+=sv[q];
        atomicAdd(&d_e[32+batch[n]], t);
    }
    float gh2=0.f;
    #pragma unroll
    for (int q=0;q<16;q++) gh2 = fmaf(w_m1[tx*16+q], sdz[q], gh2);
    sg2[tx]=gh2;
    __syncthreads();
    float ga0=0.f, ga1=0.f, ga2=0.f, gh1=w_r0[tx];
    for (int d=0;d<64;d++){
        float g = sg2[d];
        ga0 = fmaf(wo0[tx*64+d], g, ga0);
        ga1 = fmaf(wo4[tx*64+d], g, ga1);
        ga2 = fmaf(wo9[tx*64+d], g, ga2);
        gh1 = fmaf(wsc[tx*64+d], g, gh1);
    }
    d_gagg1[n*64+tx]=ga0;
    d_gagg1[N64+n*64+tx]=ga1;
    d_gagg1[2*N64+n*64+tx]=ga2;
    d_gh1_0[n*64+tx]=gh1;
}

// ----------------------------------------------------------------------------
__global__ void k_int1_bwd_edge(const int* __restrict__ ei){
    int gtid = blockIdx.x*blockDim.x + threadIdx.x;
    int e = gtid>>5, lane = gtid&31;
    int s = ei[e], t = ei[NE+e];
    float y[8];
    #pragma unroll
    for (int i=0;i<8;i++) y[i]=d_Y[e*8+i];
    float tY[8]={0,0,0,0,0,0,0,0};
    #pragma unroll
    for (int h=0;h<2;h++){
        int c = lane + 32*h;
        float g0 = d_gagg1[t*64+c];
        float g1 = d_gagg1[N64+t*64+c];
        float g2 = d_gagg1[2*N64+t*64+c];
        float r0 = d_R1[e*192+c], r1 = d_R1[e*192+64+c], r2 = d_R1[e*192+128+c];
        float h0v = d_hup1_0[s*64+c];
        const float* h1v = d_hup1_1 + (s*64+c)*3;
        const float* h2v = d_hup1_2 + (s*64+c)*5;
        float s1 = y[0]*h1v[0]+y[1]*h1v[1]+y[2]*h1v[2];
        float s2 = y[3]*h2v[0]+y[4]*h2v[1]+y[5]*h2v[2]+y[6]*h2v[3]+y[7]*h2v[4];
        d_R1[e*192+c]     = K0C*h0v*g0;
        d_R1[e*192+64+c]  = K4N*s1*g1;
        d_R1[e*192+128+c] = K9N*s2*g2;
        atomicAdd(&d_gHup1_0[s*64+c], K0C*r0*g0);
        float a1 = K4N*r1*g1;
        float a2 = K9N*r2*g2;
        float* p1 = d_gHup1_1 + (s*64+c)*3;
        float* p2 = d_gHup1_2 + (s*64+c)*5;
        #pragma unroll
        for (int i=0;i<3;i++){ atomicAdd(p1+i, a1*y[i]);   tY[i]   = fmaf(a1,h1v[i],tY[i]); }
        #pragma unroll
        for (int i=0;i<5;i++){ atomicAdd(p2+i, a2*y[3+i]); tY[3+i] = fmaf(a2,h2v[i],tY[3+i]); }
    }
    #pragma unroll
    for (int i=0;i<8;i++){
        float v=tY[i];
        #pragma unroll
        for (int off=16;off>0;off>>=1) v += __shfl_xor_sync(0xffffffffu, v, off);
        tY[i]=v;
    }
    if (lane==0){
        #pragma unroll
        for (int i=0;i<8;i++) d_gY[e*8+i]=tY[i];
    }
}

// ----------------------------------------------------------------------------
__global__ void k_int1_bwd_node(const float* __restrict__ w_up1, const float* __restrict__ w_out0){
    int n=blockIdx.x, tx=threadIdx.x;
    __shared__ float sg0[64], sgh1[64], sg1[192], sg2[320];
    sg0[tx]=d_gHup1_0[n*64+tx];
    for (int i=tx;i<192;i+=64) sg1[i]=d_gHup1_1[n*192+i];
    for (int i=tx;i<320;i+=64) sg2[i]=d_gHup1_2[n*320+i];
    __syncthreads();
    float gh1 = d_gh1_0[n*64+tx];
    for (int d=0;d<64;d++) gh1 = fmaf(sg0[d], w_up1[tx*64+d], gh1);
    sgh1[tx]=gh1;
    __syncthreads();
    float ga=0.f;
    for (int d=0;d<64;d++) ga = fmaf(w_out0[tx*64+d], sgh1[d], ga);
    d_gagg0_0[n*64+tx]=ga;
    float b0=0.f,b1=0.f,b2=0.f;
    for (int d=0;d<64;d++){
        float w = d_W01[tx*64+d];
        b0=fmaf(sg1[d*3+0],w,b0); b1=fmaf(sg1[d*3+1],w,b1); b2=fmaf(sg1[d*3+2],w,b2);
    }
    float* o1 = d_gagg0_1 + (n*64+tx)*3;
    o1[0]=b0; o1[1]=b1; o1[2]=b2;
    float c0=0.f,c1=0.f,c2=0.f,c3=0.f,c4=0.f;
    for (int d=0;d<64;d++){
        float w = d_W02[tx*64+d];
        c0=fmaf(sg2[d*5+0],w,c0); c1=fmaf(sg2[d*5+1],w,c1);
        c2=fmaf(sg2[d*5+2],w,c2); c3=fmaf(sg2[d*5+3],w,c3);
        c4=fmaf(sg2[d*5+4],w,c4);
    }
    float* o2 = d_gagg0_2 + (n*64+tx)*5;
    o2[0]=c0; o2[1]=c1; o2[2]=c2; o2[3]=c3; o2[4]=c4;
}

// ----------------------------------------------------------------------------
__global__ void k_int0_bwd_edge(const int* __restrict__ ei){
    int gtid = blockIdx.x*blockDim.x + threadIdx.x;
    int e = gtid>>5, lane = gtid&31;
    int s = ei[e], t = ei[NE+e];
    float y[8];
    #pragma unroll
    for (int i=0;i<8;i++) y[i]=d_Y[e*8+i];
    float tY[8]={0,0,0,0,0,0,0,0};
    #pragma unroll
    for (int h=0;h<2;h++){
        int c = lane + 32*h;
        float hp = d_hup0[s*64+c];
        float ga0 = d_gagg0_0[t*64+c];
        const float* ga1 = d_gagg0_1 + (t*64+c)*3;
        const float* ga2 = d_gagg0_2 + (t*64+c)*5;
        float r1 = d_R0[e*192+64+c], r2 = d_R0[e*192+128+c];
        float s1 = y[0]*ga1[0]+y[1]*ga1[1]+y[2]*ga1[2];
        float s2 = y[3]*ga2[0]+y[4]*ga2[1]+y[5]*ga2[2]+y[6]*ga2[3]+y[7]*ga2[4];
        d_R0[e*192+c]     = K0C*hp*ga0;
        d_R0[e*192+64+c]  = K1C*hp*s1;
        d_R0[e*192+128+c] = K2C*hp*s2;
        float b1 = K1C*hp*r1;
        float b2 = K2C*hp*r2;
        #pragma unroll
        for (int i=0;i<3;i++) tY[i]   = fmaf(b1, ga1[i], tY[i]);
        #pragma unroll
        for (int i=0;i<5;i++) tY[3+i] = fmaf(b2, ga2[i], tY[3+i]);
    }
    #pragma unroll
    for (int i=0;i<8;i++){
        float v=tY[i];
        #pragma unroll
        for (int off=16;off>0;off>>=1) v += __shfl_xor_sync(0xffffffffu, v, off);
        tY[i]=v;
    }
    if (lane==0){
        #pragma unroll
        for (int i=0;i<8;i++) d_gY[e*8+i] += tY[i];
    }
}

// ----------------------------------------------------------------------------
__global__ void k_force_edge(const int* __restrict__ ei, float* __restrict__ out){
    int e = blockIdx.x*blockDim.x + threadIdx.x;
    if (e >= NE) return;
    int s = ei[e], t = ei[NE+e];
    float vx=d_vec[e*3+0], vy=d_vec[e*3+1], vz=d_vec[e*3+2];
    float r = d_r[e], inv = 1.0f/r;
    float x=vx*inv, y=vy*inv, z=vz*inv;
    const float* gy = d_gY + e*8;
    float gux = S3f*gy[2] + S15f*(y*gy[3] + z*gy[6] + x*gy[7]);
    float guy = S3f*gy[0] + S15f*(x*gy[3] + z*gy[4] - y*gy[7]);
    float guz = S3f*gy[1] + S15f*(y*gy[4] + x*gy[6]) + 3.f*S5f*z*gy[5];
    float uu = r*0.2f, fc=0.f, dfc=0.f;
    if (uu < 1.0f){
        float u2=uu*uu, u4=u2*u2, u5=u4*uu, u6=u5*uu, u7=u6*uu;
        fc  = 1.f - 21.f*u5 + 35.f*u6 - 15.f*u7;
        dfc = (-105.f*u4 + 210.f*u5 - 105.f*u6)*0.2f;
    }
    float c0 = sqrtf(0.4f);
    float gr = 0.f;
    const float* gf = d_gfeat + e*8;
    #pragma unroll
    for (int q=1;q<=8;q++){
        float a = (float)q*(PIf/5.0f);
        float sa = sinf(a*r), ca = cosf(a*r);
        float df = c0*((a*ca*inv - sa*inv*inv)*fc + sa*inv*dfc);
        gr = fmaf(gf[q-1], df, gr);
    }
    float dot = x*gux + y*guy + z*guz;
    float gvx = (gux - x*dot)*inv + gr*x;
    float gvy = (guy - y*dot)*inv + gr*y;
    float gvz = (guz - z*dot)*inv + gr*z;
    float* F = out + 64;
    atomicAdd(&F[t*3+0], -gvx); atomicAdd(&F[t*3+1], -gvy); atomicAdd(&F[t*3+2], -gvz);
    atomicAdd(&F[s*3+0],  gvx); atomicAdd(&F[s*3+1],  gvy); atomicAdd(&F[s*3+2],  gvz);
}

// ----------------------------------------------------------------------------
__global__ void k_finalize(float* __restrict__ out){
    int g = threadIdx.x;
    if (g >= 16) return;
    float e0=d_e[g], e1=d_e[16+g], e2=d_e[32+g];
    out[g] = e0+e1+e2;
    out[16+g*3+0]=e0; out[16+g*3+1]=e1; out[16+g*3+2]=e2;
}

// ----------------------------------------------------------------------------
extern "C" void kernel_launch(void* const* d_in, const int* in_sizes, int n_in,
                              void* d_out, int out_size){
    const float* pos    = (const float*)d_in[0];
    const float* attrs  = (const float*)d_in[1];
    const float* shifts = (const float*)d_in[2];
    const float* aener  = (const float*)d_in[3];
    const float* w_emb  = (const float*)d_in[4];
    const float* w_up0  = (const float*)d_in[5];
    const float* r0w1   = (const float*)d_in[6];
    const float* r0w2   = (const float*)d_in[7];
    const float* r0w3   = (const float*)d_in[8];
    const float* r0w4   = (const float*)d_in[9];
    const float* w_out0 = (const float*)d_in[10];
    const float* w_sc0  = (const float*)d_in[11];
    const float* w_r0   = (const float*)d_in[12];
    const float* w_up1  = (const float*)d_in[13];
    const float* r1w1   = (const float*)d_in[14];
    const float* r1w2   = (const float*)d_in[15];
    const float* r1w3   = (const float*)d_in[16];
    const float* r1w4   = (const float*)d_in[17];
    const float* w_out1 = (const float*)d_in[18];
    const float* w_sc1  = (const float*)d_in[19];
    const float* w_m1   = (const float*)d_in[20];
    const float* w_m2   = (const float*)d_in[21];
    const int*   ei     = (const int*)d_in[22];
    const int*   batch  = (const int*)d_in[23];
    float* out = (float*)d_out;

    k_zero<<<2048,256>>>(out);
    k_transpose<<<48,256>>>(r0w2,r0w3,r0w4,r1w2,r1w3,r1w4);
    k_precW<<<dim3(64,2),64>>>(w_out0, w_up1);
    k_edge_geom<<<625,256>>>(pos, shifts, ei);
    k_node_init<<<NN,64>>>(attrs, w_emb, w_up0, aener, batch);
    k_mlp_fwd<<<NE/8, dim3(64,8)>>>(r0w1,r0w2,r0w3,r0w4, 192, 64, 128, 0);
    k_mlp_fwd<<<NE/8, dim3(64,8)>>>(r1w1,r1w2,r1w3,r1w4, 832, 256, 576, 1);
    k_int0_edge<<<NE*64/256,256>>>(ei);
    k_int0_node<<<NN,64>>>(w_emb, w_out0, w_sc0, w_r0, w_up1, batch);
    k_int1_edge<<<NE*64/256,256>>>(ei);
    k_int1_node<<<NN,64>>>(w_out1, w_sc1, w_m1, w_m2, w_r0, batch);
    k_int1_bwd_edge<<<NE*32/256,256>>>(ei);
    k_int1_bwd_node<<<NN,64>>>(w_up1, w_out0);
    k_int0_bwd_edge<<<NE*32/256,256>>>(ei);
    k_mlp_bwd<<<NE/8, dim3(64,8)>>>(r1w1, 1, 0);
    k_mlp_bwd<<<NE/8, dim3(64,8)>>>(r0w1, 0, 1);
    k_force_edge<<<625,256>>>(ei, out);
    k_finalize<<<1,16>>>(out);
}

// round 4
// speedup vs baseline: 1.3354x; 1.3354x over previous
#include <cuda_runtime.h>
#include <math.h>

#define NE 160000
#define NN 10000
#define N64 (NN*64)

#define S3f  1.7320508075688772f
#define S5f  2.2360679774997896f
#define S15f 3.8729833462074170f
#define PIf  3.14159265358979323846f
#define K0C  (0.0625f)
#define K1C  (0.0625f/S3f)
#define K2C  (0.0625f/S5f)
#define K4N  (-0.0625f/S3f)
#define K9N  (0.0625f/S5f)

// ---------------- scratch ----------------
__device__ float d_vec[NE*3];
__device__ float d_r[NE];
__device__ float d_Y[NE*8];
__device__ float d_feat[NE*8];
__device__ float d_gfeat[NE*8];
__device__ float d_gY[NE*8];
__device__ float d_gvec[NE*3];
__device__ float d_z0a[NE*64], d_z0b[NE*64], d_z0c[NE*64];
__device__ float d_z1a[NE*64], d_z1b[NE*64], d_z1c[NE*64];
__device__ float d_R0[NE*192];   // reused in-place as gR0
__device__ float d_R1[NE*192];   // reused in-place as gR1

__device__ int   d_sp[NN];
__device__ float d_hup0[N64];
__device__ float d_h1_0[N64];
__device__ float d_hup1_0[N64];
__device__ float d_hup1_1[NN*192];
__device__ float d_hup1_2[NN*320];
__device__ float d_agg0_0[N64];
__device__ float d_agg0_1[NN*192];
__device__ float d_agg0_2[NN*320];
__device__ float d_agg1[3*N64];
__device__ float d_gagg1[3*N64];
__device__ float d_gh1_0[N64];
__device__ float d_gHup1_0[N64];
__device__ float d_gHup1_1[NN*192];
__device__ float d_gHup1_2[NN*320];
__device__ float d_gagg0_0[N64];
__device__ float d_gagg0_1[NN*192];
__device__ float d_gagg0_2[NN*320];
__device__ float d_W01[4096], d_W02[4096];
__device__ float d_e[48];

// CSR
__device__ int d_deg_r[NN], d_deg_s[NN];
__device__ int d_off_r[NN+1], d_off_s[NN+1];
__device__ int d_cur_r[NN], d_cur_s[NN];
__device__ int d_csr_r[NE], d_csr_s[NE];

__device__ __forceinline__ float siluf(float x){ float s=1.f/(1.f+expf(-x)); return x*s; }
__device__ __forceinline__ float dsiluf(float x){ float s=1.f/(1.f+expf(-x)); return s*(1.f+x*(1.f-s)); }

// ----------------------------------------------------------------------------
__global__ void k_zero(){
    int i = blockIdx.x*blockDim.x + threadIdx.x;
    int st = gridDim.x*blockDim.x;
    for (int j=i;j<48;j+=st) d_e[j]=0.f;
    for (int j=i;j<NN;j+=st){ d_deg_r[j]=0; d_deg_s[j]=0; }
}

__global__ void k_hist(const int* __restrict__ ei){
    int e = blockIdx.x*blockDim.x + threadIdx.x;
    atomicAdd(&d_deg_r[ei[NE+e]],1);
    atomicAdd(&d_deg_s[ei[e]],1);
}

__global__ void k_scan(){
    __shared__ int sh[1024];
    int t = threadIdx.x;
    for (int w=0; w<2; w++){
        int* deg = w? d_deg_s: d_deg_r;
        int* off = w? d_off_s: d_off_r;
        int* cur = w? d_cur_s: d_cur_r;
        int base = t*10, s=0;
        #pragma unroll
        for (int i=0;i<10;i++){ int idx=base+i; if (idx<NN) s+=deg[idx]; }
        sh[t]=s;
        __syncthreads();
        for (int d=1; d<1024; d<<=1){
            int v = (t>=d)? sh[t-d]:0;
            __syncthreads();
            sh[t]+=v;
            __syncthreads();
        }
        int run = sh[t]-s;
        #pragma unroll
        for (int i=0;i<10;i++){ int idx=base+i; if (idx<NN){ off[idx]=run; cur[idx]=run; run+=deg[idx]; } }
        if (t==0) off[NN]=NE;
        __syncthreads();
    }
}

__global__ void k_csr_fill(const int* __restrict__ ei){
    int e = blockIdx.x*blockDim.x + threadIdx.x;
    int p = atomicAdd(&d_cur_r[ei[NE+e]],1); d_csr_r[p]=e;
    int q = atomicAdd(&d_cur_s[ei[e]],1);    d_csr_s[q]=e;
}

// ----------------------------------------------------------------------------
__global__ void k_precW(const float* __restrict__ w_out0, const float* __restrict__ w_up1){
    int c = blockIdx.x, l = blockIdx.y+1, d2 = threadIdx.x;
    const float* wo = w_out0 + l*4096;
    const float* wu = w_up1  + l*4096;
    float a=0.f;
    for (int d=0;d<64;d++) a = fmaf(wo[c*64+d], wu[d*64+d2], a);
    if (l==1) d_W01[c*64+d2]=a; else d_W02[c*64+d2]=a;
}

// ----------------------------------------------------------------------------
__global__ void k_edge_geom(const float* __restrict__ pos, const float* __restrict__ shifts,
                            const int* __restrict__ ei){
    int e = blockIdx.x*blockDim.x + threadIdx.x;
    if (e >= NE) return;
    int s = ei[e], t = ei[NE+e];
    float vx = pos[t*3+0]-pos[s*3+0]+shifts[e*3+0];
    float vy = pos[t*3+1]-pos[s*3+1]+shifts[e*3+1];
    float vz = pos[t*3+2]-pos[s*3+2]+shifts[e*3+2];
    float r  = sqrtf(vx*vx+vy*vy+vz*vz + 1e-12f);
    d_vec[e*3+0]=vx; d_vec[e*3+1]=vy; d_vec[e*3+2]=vz; d_r[e]=r;
    float inv = 1.0f/r;
    float x=vx*inv, y=vy*inv, z=vz*inv;
    d_Y[e*8+0]=S3f*y;  d_Y[e*8+1]=S3f*z;  d_Y[e*8+2]=S3f*x;
    d_Y[e*8+3]=S15f*x*y; d_Y[e*8+4]=S15f*y*z;
    d_Y[e*8+5]=0.5f*S5f*(3.f*z*z-1.f);
    d_Y[e*8+6]=S15f*x*z; d_Y[e*8+7]=0.5f*S15f*(x*x-y*y);
    float uu = r*0.2f, fc = 0.f;
    if (uu < 1.0f){
        float u2=uu*uu, u4=u2*u2, u5=u4*uu, u6=u5*uu, u7=u6*uu;
        fc = 1.f - 21.f*u5 + 35.f*u6 - 15.f*u7;
    }
    float c0 = sqrtf(0.4f);
    #pragma unroll
    for (int q=1;q<=8;q++){
        float a = (float)q*(PIf/5.0f);
        d_feat[e*8+q-1] = c0*sinf(a*r)*inv*fc;
    }
}

// ------------------------- register-blocked MLPs ----------------------------
#define MM64(SRC) do{ \
    _Pragma("unroll") for(int i=0;i<8;i++) acc[i]=0.f; \
    _Pragma("unroll") for(int k0=0;k0<64;k0+=4){ \
        _Pragma("unroll") for(int i=0;i<8;i++){ \
            float4 a4=*(const float4*)&SRC[r0+i][k0]; \
            acc[i]=fmaf(a4.x,wc[k0],acc[i]); acc[i]=fmaf(a4.y,wc[k0+1],acc[i]); \
            acc[i]=fmaf(a4.z,wc[k0+2],acc[i]); acc[i]=fmaf(a4.w,wc[k0+3],acc[i]); } } \
}while(0)
#define FILLW() _Pragma("unroll") for(int k=0;k<64;k++) wc[k]=sW[k*65+j]

__global__ void __launch_bounds__(256) k_mlp_fwd(const float* __restrict__ w1,
        const float* __restrict__ w2, const float* __restrict__ w3,
        const float* __restrict__ w4, int w4s, int cb1, int cb2, int which){
    __shared__ float sA[32][64];
    __shared__ float sB[32][64];
    __shared__ float sW[64*65];
    int tid=threadIdx.x, j=tid&63, r0=(tid>>6)*8;
    int e0=blockIdx.x*32;
    float* za = which? d_z1a:d_z0a;
    float* zb = which? d_z1b:d_z0b;
    float* zc = which? d_z1c:d_z0c;
    float* Ro = which? d_R1:d_R0;
    { int r=tid>>3, q=tid&7; sA[r][q]=d_feat[(e0+r)*8+q]; }
    __syncthreads();
    float acc[8], wc[64];
    // L1: 8 -> 64
    #pragma unroll
    for(int i=0;i<8;i++) acc[i]=0.f;
    #pragma unroll
    for(int k=0;k<8;k++){
        float w=w1[k*64+j];
        #pragma unroll
        for(int i=0;i<8;i++) acc[i]=fmaf(sA[r0+i][k],w,acc[i]);
    }
    #pragma unroll
    for(int i=0;i<8;i++){ za[(e0+r0+i)*64+j]=acc[i]; sB[r0+i][j]=siluf(acc[i]); }
    for(int idx=tid; idx<4096; idx+=256){ int a_=idx>>6, b_=idx&63; sW[a_*65+b_]=w2[idx]; }
    __syncthreads();
    FILLW();
    MM64(sB);
    __syncthreads();
    #pragma unroll
    for(int i=0;i<8;i++){ zb[(e0+r0+i)*64+j]=acc[i]; sA[r0+i][j]=siluf(acc[i]); }
    for(int idx=tid; idx<4096; idx+=256){ int a_=idx>>6, b_=idx&63; sW[a_*65+b_]=w3[idx]; }
    __syncthreads();
    FILLW();
    MM64(sA);
    __syncthreads();
    #pragma unroll
    for(int i=0;i<8;i++){ zc[(e0+r0+i)*64+j]=acc[i]; sB[r0+i][j]=siluf(acc[i]); }
    int cbs[3]={0,cb1,cb2};
    for(int p=0;p<3;p++){
        for(int idx=tid; idx<4096; idx+=256){ int a_=idx>>6, b_=idx&63; sW[a_*65+b_]=w4[a_*w4s+cbs[p]+b_]; }
        __syncthreads();
        FILLW();
        MM64(sB);
        #pragma unroll
        for(int i=0;i<8;i++) Ro[(e0+r0+i)*192 + p*64 + j]=acc[i];
        __syncthreads();
    }
}

__global__ void __launch_bounds__(256) k_mlp_bwd(const float* __restrict__ w1,
        const float* __restrict__ w2, const float* __restrict__ w3,
        const float* __restrict__ w4, int w4s, int cb1, int cb2, int which, int accF){
    __shared__ float sA[32][64];
    __shared__ float sB[32][64];
    __shared__ float sW[64*65];
    int tid=threadIdx.x, j=tid&63, r0=(tid>>6)*8;
    int e0=blockIdx.x*32;
    const float* za = which? d_z1a:d_z0a;
    const float* zb = which? d_z1b:d_z0b;
    const float* zc = which? d_z1c:d_z0c;
    const float* gR = which? d_R1:d_R0;
    float acc[8], wc[64], g3[8];
    int cbs[3]={0,cb1,cb2};
    #pragma unroll
    for(int i=0;i<8;i++) g3[i]=0.f;
    for(int p=0;p<3;p++){
        #pragma unroll
        for(int i=0;i<8;i++) sA[r0+i][j]=gR[(e0+r0+i)*192+p*64+j];
        for(int idx=tid; idx<4096; idx+=256){ int a_=idx>>6, b_=idx&63; sW[b_*65+a_]=w4[a_*w4s+cbs[p]+b_]; }
        __syncthreads();
        FILLW();
        MM64(sA);
        #pragma unroll
        for(int i=0;i<8;i++) g3[i]+=acc[i];
        __syncthreads();
    }
    #pragma unroll
    for(int i=0;i<8;i++) sB[r0+i][j]=g3[i]*dsiluf(zc[(e0+r0+i)*64+j]);
    for(int idx=tid; idx<4096; idx+=256){ int a_=idx>>6, b_=idx&63; sW[b_*65+a_]=w3[idx]; }
    __syncthreads();
    FILLW();
    MM64(sB);
    __syncthreads();
    #pragma unroll
    for(int i=0;i<8;i++) sA[r0+i][j]=acc[i]*dsiluf(zb[(e0+r0+i)*64+j]);
    for(int idx=tid; idx<4096; idx+=256){ int a_=idx>>6, b_=idx&63; sW[b_*65+a_]=w2[idx]; }
    __syncthreads();
    FILLW();
    MM64(sA);
    __syncthreads();
    #pragma unroll
    for(int i=0;i<8;i++) sB[r0+i][j]=acc[i]*dsiluf(za[(e0+r0+i)*64+j]);
    __syncthreads();
    if (j<8){
        #pragma unroll
        for(int i=0;i<8;i++){
            float gf=0.f;
            for(int k=0;k<64;k++) gf=fmaf(sB[r0+i][k], w1[j*64+k], gf);
            int e=e0+r0+i;
            if (accF) d_gfeat[e*8+j]+=gf; else d_gfeat[e*8+j]=gf;
        }
    }
}

// ----------------------------------------------------------------------------
__global__ void k_node_init(const float* __restrict__ attrs, const float* __restrict__ w_emb,
                            const float* __restrict__ w_up0, const float* __restrict__ aener,
                            const int* __restrict__ batch){
    int n = blockIdx.x, c = threadIdx.x;
    __shared__ int ssp;
    __shared__ float sh0[64];
    if (c==0){
        int sp=0;
        for (int q=0;q<10;q++) if (attrs[n*10+q] > 0.5f) sp=q;
        ssp=sp; d_sp[n]=sp;
        atomicAdd(&d_e[batch[n]], aener[sp]);
    }
    __syncthreads();
    sh0[c]=w_emb[ssp*64+c];
    __syncthreads();
    float a=0.f;
    for (int k=0;k<64;k++) a = fmaf(sh0[k], w_up0[k*64+c], a);
    d_hup0[n*64+c]=a;
}

// ----------------------------------------------------------------------------
__global__ void k_int0_agg(const int* __restrict__ ei){
    int n = blockIdx.x, c = threadIdx.x;
    int b0=d_off_r[n], b1=d_off_r[n+1];
    float a0=0.f, a1[3]={0,0,0}, a2[5]={0,0,0,0,0};
    for (int q=b0;q<b1;q++){
        int e=d_csr_r[q]; int s=ei[e];
        float hup=d_hup0[s*64+c];
        const float* Rb=d_R0+e*192;
        const float* Ye=d_Y+e*8;
        a0 = fmaf(hup*K0C, Rb[c], a0);
        float m1=hup*Rb[64+c]*K1C;
        #pragma unroll
        for (int i=0;i<3;i++) a1[i]=fmaf(m1,Ye[i],a1[i]);
        float m2=hup*Rb[128+c]*K2C;
        #pragma unroll
        for (int i=0;i<5;i++) a2[i]=fmaf(m2,Ye[3+i],a2[i]);
    }
    d_agg0_0[n*64+c]=a0;
    #pragma unroll
    for (int i=0;i<3;i++) d_agg0_1[(n*64+c)*3+i]=a1[i];
    #pragma unroll
    for (int i=0;i<5;i++) d_agg0_2[(n*64+c)*5+i]=a2[i];
}

// ----------------------------------------------------------------------------
__global__ void k_int0_node(const float* __restrict__ w_emb, const float* __restrict__ w_out0,
                            const float* __restrict__ w_sc0, const float* __restrict__ w_r0,
                            const float* __restrict__ w_up1, const int* __restrict__ batch){
    int n=blockIdx.x, tx=threadIdx.x;
    __shared__ float sA0[64], sA1[192], sA2[320], sh0[64], sh1[64];
    __shared__ float sred[2];
    int sp = d_sp[n];
    sA0[tx]=d_agg0_0[n*64+tx];
    sh0[tx]=w_emb[sp*64+tx];
    for (int i=tx;i<192;i+=64) sA1[i]=d_agg0_1[n*192+i];
    for (int i=tx;i<320;i+=64) sA2[i]=d_agg0_2[n*320+i];
    __syncthreads();
    const float* wsc = w_sc0 + sp*4096;
    float acc=0.f;
    for (int c=0;c<64;c++){
        acc = fmaf(sA0[c], w_out0[c*64+tx], acc);
        acc = fmaf(sh0[c], wsc[c*64+tx], acc);
    }
    d_h1_0[n*64+tx]=acc;
    sh1[tx]=acc;
    float ev = acc*w_r0[tx];
    #pragma unroll
    for (int off=16;off>0;off>>=1) ev += __shfl_xor_sync(0xffffffffu, ev, off);
    if ((tx&31)==0) sred[tx>>5]=ev;
    __syncthreads();
    if (tx==0) atomicAdd(&d_e[16+batch[n]], sred[0]+sred[1]);
    float a=0.f;
    for (int c=0;c<64;c++) a = fmaf(sh1[c], w_up1[c*64+tx], a);
    d_hup1_0[n*64+tx]=a;
    float b0=0.f,b1=0.f,b2=0.f;
    for (int c=0;c<64;c++){
        float w = d_W01[c*64+tx];
        b0=fmaf(sA1[c*3+0],w,b0); b1=fmaf(sA1[c*3+1],w,b1); b2=fmaf(sA1[c*3+2],w,b2);
    }
    float* h1 = d_hup1_1 + (n*64+tx)*3;
    h1[0]=b0; h1[1]=b1; h1[2]=b2;
    float e0_=0.f,e1_=0.f,e2_=0.f,e3_=0.f,e4_=0.f;
    for (int c=0;c<64;c++){
        float w = d_W02[c*64+tx];
        e0_=fmaf(sA2[c*5+0],w,e0_); e1_=fmaf(sA2[c*5+1],w,e1_);
        e2_=fmaf(sA2[c*5+2],w,e2_); e3_=fmaf(sA2[c*5+3],w,e3_);
        e4_=fmaf(sA2[c*5+4],w,e4_);
    }
    float* h2 = d_hup1_2 + (n*64+tx)*5;
    h2[0]=e0_; h2[1]=e1_; h2[2]=e2_; h2[3]=e3_; h2[4]=e4_;
}

// ----------------------------------------------------------------------------
__global__ void k_int1_agg(const int* __restrict__ ei){
    int n = blockIdx.x, c = threadIdx.x;
    int b0=d_off_r[n], b1=d_off_r[n+1];
    float a0=0.f, a1=0.f, a2=0.f;
    for (int q=b0;q<b1;q++){
        int e=d_csr_r[q]; int s=ei[e];
        const float* Rb=d_R1+e*192;
        const float* Ye=d_Y+e*8;
        a0 = fmaf(d_hup1_0[s*64+c]*K0C, Rb[c], a0);
        const float* hv1 = d_hup1_1 + (s*64+c)*3;
        float S1 = Ye[0]*hv1[0]+Ye[1]*hv1[1]+Ye[2]*hv1[2];
        a1 = fmaf(S1*K4N, Rb[64+c], a1);
        const float* hv2 = d_hup1_2 + (s*64+c)*5;
        float S2 = Ye[3]*hv2[0]+Ye[4]*hv2[1]+Ye[5]*hv2[2]+Ye[6]*hv2[3]+Ye[7]*hv2[4];
        a2 = fmaf(S2*K9N, Rb[128+c], a2);
    }
    d_agg1[n*64+c]=a0;
    d_agg1[N64+n*64+c]=a1;
    d_agg1[2*N64+n*64+c]=a2;
}

// ----------------------------------------------------------------------------
__global__ void k_int1_node(const float* __restrict__ w_out1, const float* __restrict__ w_sc1,
                            const float* __restrict__ w_m1, const float* __restrict__ w_m2,
                            const float* __restrict__ w_r0, const int* __restrict__ batch){
    int n=blockIdx.x, tx=threadIdx.x;
    __shared__ float sA0[64], sA1[64], sA2[64], sh1[64], sh2[64], sg2[64];
    __shared__ float sv[16], sdz[16];
    int sp=d_sp[n];
    sA0[tx]=d_agg1[n*64+tx];
    sA1[tx]=d_agg1[N64+n*64+tx];
    sA2[tx]=d_agg1[2*N64+n*64+tx];
    sh1[tx]=d_h1_0[n*64+tx];
    __syncthreads();
    const float* wo0 = w_out1;
    const float* wo4 = w_out1 + 4*4096;
    const float* wo9 = w_out1 + 9*4096;
    const float* wsc = w_sc1 + sp*4096;
    float h2=0.f;
    for (int c=0;c<64;c++){
        h2 = fmaf(sA0[c], wo0[c*64+tx], h2);
        h2 = fmaf(sA1[c], wo4[c*64+tx], h2);
        h2 = fmaf(sA2[c], wo9[c*64+tx], h2);
        h2 = fmaf(sh1[c], wsc[c*64+tx], h2);
    }
    sh2[tx]=h2;
    __syncthreads();
    if (tx < 16){
        float z=0.f;
        for (int d=0;d<64;d++) z = fmaf(sh2[d], w_m1[d*16+tx], z);
        float s=1.f/(1.f+expf(-z));
        sv[tx]  = z*s*w_m2[tx];
        sdz[tx] = s*(1.f+z*(1.f-s))*w_m2[tx];
    }
    __syncthreads();
    if (tx==0){
        float t=0.f;
        for (int q=0;q<16;q++) t+=sv[q];
        atomicAdd(&d_e[32+batch[n]], t);
    }
    float gh2=0.f;
    #pragma unroll
    for (int q=0;q<16;q++) gh2 = fmaf(w_m1[tx*16+q], sdz[q], gh2);
    sg2[tx]=gh2;
    __syncthreads();
    float ga0=0.f, ga1=0.f, ga2=0.f, gh1=w_r0[tx];
    for (int d=0;d<64;d++){
        float g = sg2[d];
        ga0 = fmaf(wo0[tx*64+d], g, ga0);
        ga1 = fmaf(wo4[tx*64+d], g, ga1);
        ga2 = fmaf(wo9[tx*64+d], g, ga2);
        gh1 = fmaf(wsc[tx*64+d], g, gh1);
    }
    d_gagg1[n*64+tx]=ga0;
    d_gagg1[N64+n*64+tx]=ga1;
    d_gagg1[2*N64+n*64+tx]=ga2;
    d_gh1_0[n*64+tx]=gh1;
}

// ----------------------------------------------------------------------------
// per-node (sender) gather: gHup1 = sum over outgoing edges. Reads ORIGINAL R1.
__global__ void k_int1_bwd_send(const int* __restrict__ ei){
    int n = blockIdx.x, c = threadIdx.x;
    int b0=d_off_s[n], b1=d_off_s[n+1];
    float g0a=0.f, g1a[3]={0,0,0}, g2a[5]={0,0,0,0,0};
    for (int q=b0;q<b1;q++){
        int e=d_csr_s[q]; int t=ei[NE+e];
        float g0=d_gagg1[t*64+c];
        float g1=d_gagg1[N64+t*64+c];
        float g2=d_gagg1[2*N64+t*64+c];
        const float* Rb=d_R1+e*192;
        const float* Ye=d_Y+e*8;
        g0a = fmaf(K0C*Rb[c], g0, g0a);
        float a1=K4N*Rb[64+c]*g1;
        #pragma unroll
        for (int i=0;i<3;i++) g1a[i]=fmaf(a1,Ye[i],g1a[i]);
        float a2=K9N*Rb[128+c]*g2;
        #pragma unroll
        for (int i=0;i<5;i++) g2a[i]=fmaf(a2,Ye[3+i],g2a[i]);
    }
    d_gHup1_0[n*64+c]=g0a;
    #pragma unroll
    for (int i=0;i<3;i++) d_gHup1_1[(n*64+c)*3+i]=g1a[i];
    #pragma unroll
    for (int i=0;i<5;i++) d_gHup1_2[(n*64+c)*5+i]=g2a[i];
}

// ----------------------------------------------------------------------------
// per-edge: gR1 (overwrites d_R1) and gY. Must run AFTER k_int1_bwd_send.
__global__ void k_int1_bwd_edge(const int* __restrict__ ei){
    int gtid = blockIdx.x*blockDim.x + threadIdx.x;
    int e = gtid>>5, lane = gtid&31;
    int s = ei[e], t = ei[NE+e];
    float y[8];
    #pragma unroll
    for (int i=0;i<8;i++) y[i]=d_Y[e*8+i];
    float tY[8]={0,0,0,0,0,0,0,0};
    #pragma unroll
    for (int h=0;h<2;h++){
        int c = lane + 32*h;
        float g0 = d_gagg1[t*64+c];
        float g1 = d_gagg1[N64+t*64+c];
        float g2 = d_gagg1[2*N64+t*64+c];
        float r1 = d_R1[e*192+64+c], r2 = d_R1[e*192+128+c];
        float h0v = d_hup1_0[s*64+c];
        const float* h1v = d_hup1_1 + (s*64+c)*3;
        const float* h2v = d_hup1_2 + (s*64+c)*5;
        float s1 = y[0]*h1v[0]+y[1]*h1v[1]+y[2]*h1v[2];
        float s2 = y[3]*h2v[0]+y[4]*h2v[1]+y[5]*h2v[2]+y[6]*h2v[3]+y[7]*h2v[4];
        d_R1[e*192+c]     = K0C*h0v*g0;
        d_R1[e*192+64+c]  = K4N*s1*g1;
        d_R1[e*192+128+c] = K9N*s2*g2;
        float a1 = K4N*r1*g1;
        float a2 = K9N*r2*g2;
        #pragma unroll
        for (int i=0;i<3;i++) tY[i]   = fmaf(a1,h1v[i],tY[i]);
        #pragma unroll
        for (int i=0;i<5;i++) tY[3+i] = fmaf(a2,h2v[i],tY[3+i]);
    }
    #pragma unroll
    for (int i=0;i<8;i++){
        float v=tY[i];
        #pragma unroll
        for (int off=16;off>0;off>>=1) v += __shfl_xor_sync(0xffffffffu, v, off);
        tY[i]=v;
    }
    if (lane==0){
        #pragma unroll
        for (int i=0;i<8;i++) d_gY[e*8+i]=tY[i];
    }
}

// ----------------------------------------------------------------------------
__global__ void k_int1_bwd_node(const float* __restrict__ w_up1, const float* __restrict__ w_out0){
    int n=blockIdx.x, tx=threadIdx.x;
    __shared__ float sg0[64], sgh1[64], sg1[192], sg2[320];
    sg0[tx]=d_gHup1_0[n*64+tx];
    for (int i=tx;i<192;i+=64) sg1[i]=d_gHup1_1[n*192+i];
    for (int i=tx;i<320;i+=64) sg2[i]=d_gHup1_2[n*320+i];
    __syncthreads();
    float gh1 = d_gh1_0[n*64+tx];
    for (int d=0;d<64;d++) gh1 = fmaf(sg0[d], w_up1[tx*64+d], gh1);
    sgh1[tx]=gh1;
    __syncthreads();
    float ga=0.f;
    for (int d=0;d<64;d++) ga = fmaf(w_out0[tx*64+d], sgh1[d], ga);
    d_gagg0_0[n*64+tx]=ga;
    float b0=0.f,b1=0.f,b2=0.f;
    for (int d=0;d<64;d++){
        float w = d_W01[tx*64+d];
        b0=fmaf(sg1[d*3+0],w,b0); b1=fmaf(sg1[d*3+1],w,b1); b2=fmaf(sg1[d*3+2],w,b2);
    }
    float* o1 = d_gagg0_1 + (n*64+tx)*3;
    o1[0]=b0; o1[1]=b1; o1[2]=b2;
    float c0=0.f,c1=0.f,c2=0.f,c3=0.f,c4=0.f;
    for (int d=0;d<64;d++){
        float w = d_W02[tx*64+d];
        c0=fmaf(sg2[d*5+0],w,c0); c1=fmaf(sg2[d*5+1],w,c1);
        c2=fmaf(sg2[d*5+2],w,c2); c3=fmaf(sg2[d*5+3],w,c3);
        c4=fmaf(sg2[d*5+4],w,c4);
    }
    float* o2 = d_gagg0_2 + (n*64+tx)*5;
    o2[0]=c0; o2[1]=c1; o2[2]=c2; o2[3]=c3; o2[4]=c4;
}

// ----------------------------------------------------------------------------
__global__ void k_int0_bwd_edge(const int* __restrict__ ei){
    int gtid = blockIdx.x*blockDim.x + threadIdx.x;
    int e = gtid>>5, lane = gtid&31;
    int s = ei[e], t = ei[NE+e];
    float y[8];
    #pragma unroll
    for (int i=0;i<8;i++) y[i]=d_Y[e*8+i];
    float tY[8]={0,0,0,0,0,0,0,0};
    #pragma unroll
    for (int h=0;h<2;h++){
        int c = lane + 32*h;
        float hp = d_hup0[s*64+c];
        float ga0 = d_gagg0_0[t*64+c];
        const float* ga1 = d_gagg0_1 + (t*64+c)*3;
        const float* ga2 = d_gagg0_2 + (t*64+c)*5;
        float r1 = d_R0[e*192+64+c], r2 = d_R0[e*192+128+c];
        float s1 = y[0]*ga1[0]+y[1]*ga1[1]+y[2]*ga1[2];
        float s2 = y[3]*ga2[0]+y[4]*ga2[1]+y[5]*ga2[2]+y[6]*ga2[3]+y[7]*ga2[4];
        d_R0[e*192+c]     = K0C*hp*ga0;
        d_R0[e*192+64+c]  = K1C*hp*s1;
        d_R0[e*192+128+c] = K2C*hp*s2;
        float b1 = K1C*hp*r1;
        float b2 = K2C*hp*r2;
        #pragma unroll
        for (int i=0;i<3;i++) tY[i]   = fmaf(b1, ga1[i], tY[i]);
        #pragma unroll
        for (int i=0;i<5;i++) tY[3+i] = fmaf(b2, ga2[i], tY[3+i]);
    }
    #pragma unroll
    for (int i=0;i<8;i++){
        float v=tY[i];
        #pragma unroll
        for (int off=16;off>0;off>>=1) v += __shfl_xor_sync(0xffffffffu, v, off);
        tY[i]=v;
    }
    if (lane==0){
        #pragma unroll
        for (int i=0;i<8;i++) d_gY[e*8+i] += tY[i];
    }
}

// ----------------------------------------------------------------------------
__global__ void k_force_edge(const int* __restrict__ ei){
    int e = blockIdx.x*blockDim.x + threadIdx.x;
    if (e >= NE) return;
    float vx=d_vec[e*3+0], vy=d_vec[e*3+1], vz=d_vec[e*3+2];
    float r = d_r[e], inv = 1.0f/r;
    float x=vx*inv, y=vy*inv, z=vz*inv;
    const float* gy = d_gY + e*8;
    float gux = S3f*gy[2] + S15f*(y*gy[3] + z*gy[6] + x*gy[7]);
    float guy = S3f*gy[0] + S15f*(x*gy[3] + z*gy[4] - y*gy[7]);
    float guz = S3f*gy[1] + S15f*(y*gy[4] + x*gy[6]) + 3.f*S5f*z*gy[5];
    float uu = r*0.2f, fc=0.f, dfc=0.f;
    if (uu < 1.0f){
        float u2=uu*uu, u4=u2*u2, u5=u4*uu, u6=u5*uu, u7=u6*uu;
        fc  = 1.f - 21.f*u5 + 35.f*u6 - 15.f*u7;
        dfc = (-105.f*u4 + 210.f*u5 - 105.f*u6)*0.2f;
    }
    float c0 = sqrtf(0.4f);
    float gr = 0.f;
    const float* gf = d_gfeat + e*8;
    #pragma unroll
    for (int q=1;q<=8;q++){
        float a = (float)q*(PIf/5.0f);
        float sa = sinf(a*r), ca = cosf(a*r);
        float df = c0*((a*ca*inv - sa*inv*inv)*fc + sa*inv*dfc);
        gr = fmaf(gf[q-1], df, gr);
    }
    float dot = x*gux + y*guy + z*guz;
    d_gvec[e*3+0] = (gux - x*dot)*inv + gr*x;
    d_gvec[e*3+1] = (guy - y*dot)*inv + gr*y;
    d_gvec[e*3+2] = (guz - z*dot)*inv + gr*z;
}

// ----------------------------------------------------------------------------
__global__ void k_force_node(float* __restrict__ out){
    int n = blockIdx.x*4 + (threadIdx.x>>5);
    int lane = threadIdx.x&31;
    float fx=0.f, fy=0.f, fz=0.f;
    int b0=d_off_r[n], b1=d_off_r[n+1];
    for (int q=b0+lane;q<b1;q+=32){
        int e=d_csr_r[q];
        fx-=d_gvec[e*3+0]; fy-=d_gvec[e*3+1]; fz-=d_gvec[e*3+2];
    }
    b0=d_off_s[n]; b1=d_off_s[n+1];
    for (int q=b0+lane;q<b1;q+=32){
        int e=d_csr_s[q];
        fx+=d_gvec[e*3+0]; fy+=d_gvec[e*3+1]; fz+=d_gvec[e*3+2];
    }
    #pragma unroll
    for (int off=16;off>0;off>>=1){
        fx+=__shfl_xor_sync(0xffffffffu,fx,off);
        fy+=__shfl_xor_sync(0xffffffffu,fy,off);
        fz+=__shfl_xor_sync(0xffffffffu,fz,off);
    }
    if (lane==0){
        float* F = out + 64;
        F[n*3+0]=fx; F[n*3+1]=fy; F[n*3+2]=fz;
    }
}

// ----------------------------------------------------------------------------
__global__ void k_finalize(float* __restrict__ out){
    int g = threadIdx.x;
    if (g >= 16) return;
    float e0=d_e[g], e1=d_e[16+g], e2=d_e[32+g];
    out[g] = e0+e1+e2;
    out[16+g*3+0]=e0; out[16+g*3+1]=e1; out[16+g*3+2]=e2;
}

// ----------------------------------------------------------------------------
extern "C" void kernel_launch(void* const* d_in, const int* in_sizes, int n_in,
                              void* d_out, int out_size){
    const float* pos    = (const float*)d_in[0];
    const float* attrs  = (const float*)d_in[1];
    const float* shifts = (const float*)d_in[2];
    const float* aener  = (const float*)d_in[3];
    const float* w_emb  = (const float*)d_in[4];
    const float* w_up0  = (const float*)d_in[5];
    const float* r0w1   = (const float*)d_in[6];
    const float* r0w2   = (const float*)d_in[7];
    const float* r0w3   = (const float*)d_in[8];
    const float* r0w4   = (const float*)d_in[9];
    const float* w_out0 = (const float*)d_in[10];
    const float* w_sc0  = (const float*)d_in[11];
    const float* w_r0   = (const float*)d_in[12];
    const float* w_up1  = (const float*)d_in[13];
    const float* r1w1   = (const float*)d_in[14];
    const float* r1w2   = (const float*)d_in[15];
    const float* r1w3   = (const float*)d_in[16];
    const float* r1w4   = (const float*)d_in[17];
    const float* w_out1 = (const float*)d_in[18];
    const float* w_sc1  = (const float*)d_in[19];
    const float* w_m1   = (const float*)d_in[20];
    const float* w_m2   = (const float*)d_in[21];
    const int*   ei     = (const int*)d_in[22];
    const int*   batch  = (const int*)d_in[23];
    float* out = (float*)d_out;

    k_zero<<<64,256>>>();
    k_hist<<<625,256>>>(ei);
    k_scan<<<1,1024>>>();
    k_csr_fill<<<625,256>>>(ei);
    k_precW<<<dim3(64,2),64>>>(w_out0, w_up1);
    k_edge_geom<<<625,256>>>(pos, shifts, ei);
    k_node_init<<<NN,64>>>(attrs, w_emb, w_up0, aener, batch);
    k_mlp_fwd<<<NE/32,256>>>(r0w1,r0w2,r0w3,r0w4, 192, 64, 128, 0);
    k_mlp_fwd<<<NE/32,256>>>(r1w1,r1w2,r1w3,r1w4, 832, 256, 576, 1);
    k_int0_agg<<<NN,64>>>(ei);
    k_int0_node<<<NN,64>>>(w_emb, w_out0, w_sc0, w_r0, w_up1, batch);
    k_int1_agg<<<NN,64>>>(ei);
    k_int1_node<<<NN,64>>>(w_out1, w_sc1, w_m1, w_m2, w_r0, batch);
    k_int1_bwd_send<<<NN,64>>>(ei);
    k_int1_bwd_edge<<<NE*32/256,256>>>(ei);
    k_int1_bwd_node<<<NN,64>>>(w_up1, w_out0);
    k_int0_bwd_edge<<<NE*32/256,256>>>(ei);
    k_mlp_bwd<<<NE/32,256>>>(r1w1,r1w2,r1w3,r1w4, 832, 256, 576, 1, 0);
    k_mlp_bwd<<<NE/32,256>>>(r0w1,r0w2,r0w3,r0w4, 192, 64, 128, 0, 1);
    k_force_edge<<<625,256>>>(ei);
    k_force_node<<<NN/4,128>>>(out);
    k_finalize<<<1,16>>>(out);
}

// round 5
// speedup vs baseline: 2.4042x; 1.8004x over previous
#include <cuda_runtime.h>
#include <math.h>

#define NE 160000
#define NN 10000
#define N64 (NN*64)
#define NLUT 8192
#define LUT_H   (5.0f/(NLUT-1))
#define LUT_INV ((NLUT-1)/5.0f)

#define S3f  1.7320508075688772f
#define S5f  2.2360679774997896f
#define S15f 3.8729833462074170f
#define PIf  3.14159265358979323846f
#define K0C  (0.0625f)
#define K1C  (0.0625f/S3f)
#define K2C  (0.0625f/S5f)
#define K4N  (-0.0625f/S3f)
#define K9N  (0.0625f/S5f)

// ---------------- scratch ----------------
__device__ float d_vec[NE*3];
__device__ float d_r[NE];
__device__ float d_Y[NE*8];
__device__ float d_gY[NE*8];
__device__ float d_gvec[NE*3];
__device__ float d_gr[NE];
__device__ float d_R0[NE*192];   // reused in-place as gR0
__device__ float d_R1[NE*192];   // reused in-place as gR1

__device__ float d_lutR0[NLUT*192], d_lutD0[NLUT*192];
__device__ float d_lutR1[NLUT*192], d_lutD1[NLUT*192];

__device__ int   d_sp[NN];
__device__ float d_hup0[N64];
__device__ float d_h1_0[N64];
__device__ float d_hup1_0[N64];
__device__ float d_hup1_1[NN*192];
__device__ float d_hup1_2[NN*320];
__device__ float d_agg0_0[N64];
__device__ float d_agg0_1[NN*192];
__device__ float d_agg0_2[NN*320];
__device__ float d_agg1[3*N64];
__device__ float d_gagg1[3*N64];
__device__ float d_gh1_0[N64];
__device__ float d_gHup1_0[N64];
__device__ float d_gHup1_1[NN*192];
__device__ float d_gHup1_2[NN*320];
__device__ float d_gagg0_0[N64];
__device__ float d_gagg0_1[NN*192];
__device__ float d_gagg0_2[NN*320];
__device__ float d_W01[4096], d_W02[4096];
__device__ float d_e[48];

// CSR
__device__ int d_deg_r[NN], d_deg_s[NN];
__device__ int d_off_r[NN+1], d_off_s[NN+1];
__device__ int d_cur_r[NN], d_cur_s[NN];
__device__ int d_csr_r[NE], d_csr_s[NE];

__device__ __forceinline__ float siluf(float x){ float s=1.f/(1.f+expf(-x)); return x*s; }
__device__ __forceinline__ float dsiluf(float x){ float s=1.f/(1.f+expf(-x)); return s*(1.f+x*(1.f-s)); }

// ----------------------------------------------------------------------------
__global__ void k_zero(){
    int i = blockIdx.x*blockDim.x + threadIdx.x;
    int st = gridDim.x*blockDim.x;
    for (int j=i;j<48;j+=st) d_e[j]=0.f;
    for (int j=i;j<NN;j+=st){ d_deg_r[j]=0; d_deg_s[j]=0; }
}

__global__ void k_hist(const int* __restrict__ ei){
    int e = blockIdx.x*blockDim.x + threadIdx.x;
    atomicAdd(&d_deg_r[ei[NE+e]],1);
    atomicAdd(&d_deg_s[ei[e]],1);
}

__global__ void k_scan(){
    __shared__ int sh[1024];
    int t = threadIdx.x;
    for (int w=0; w<2; w++){
        int* deg = w? d_deg_s: d_deg_r;
        int* off = w? d_off_s: d_off_r;
        int* cur = w? d_cur_s: d_cur_r;
        int base = t*10, s=0;
        #pragma unroll
        for (int i=0;i<10;i++){ int idx=base+i; if (idx<NN) s+=deg[idx]; }
        sh[t]=s;
        __syncthreads();
        for (int d=1; d<1024; d<<=1){
            int v = (t>=d)? sh[t-d]:0;
            __syncthreads();
            sh[t]+=v;
            __syncthreads();
        }
        int run = sh[t]-s;
        #pragma unroll
        for (int i=0;i<10;i++){ int idx=base+i; if (idx<NN){ off[idx]=run; cur[idx]=run; run+=deg[idx]; } }
        if (t==0) off[NN]=NE;
        __syncthreads();
    }
}

__global__ void k_csr_fill(const int* __restrict__ ei){
    int e = blockIdx.x*blockDim.x + threadIdx.x;
    int p = atomicAdd(&d_cur_r[ei[NE+e]],1); d_csr_r[p]=e;
    int q = atomicAdd(&d_cur_s[ei[e]],1);    d_csr_s[q]=e;
}

// ----------------------------------------------------------------------------
__global__ void k_precW(const float* __restrict__ w_out0, const float* __restrict__ w_up1){
    int c = blockIdx.x, l = blockIdx.y+1, d2 = threadIdx.x;
    const float* wo = w_out0 + l*4096;
    const float* wu = w_up1  + l*4096;
    float a=0.f;
    for (int d=0;d<64;d++) a = fmaf(wo[c*64+d], wu[d*64+d2], a);
    if (l==1) d_W01[c*64+d2]=a; else d_W02[c*64+d2]=a;
}

// ----------------------------------------------------------------------------
__global__ void k_edge_geom(const float* __restrict__ pos, const float* __restrict__ shifts,
                            const int* __restrict__ ei){
    int e = blockIdx.x*blockDim.x + threadIdx.x;
    if (e >= NE) return;
    int s = ei[e], t = ei[NE+e];
    float vx = pos[t*3+0]-pos[s*3+0]+shifts[e*3+0];
    float vy = pos[t*3+1]-pos[s*3+1]+shifts[e*3+1];
    float vz = pos[t*3+2]-pos[s*3+2]+shifts[e*3+2];
    float r  = sqrtf(vx*vx+vy*vy+vz*vz + 1e-12f);
    d_vec[e*3+0]=vx; d_vec[e*3+1]=vy; d_vec[e*3+2]=vz; d_r[e]=r;
    float inv = 1.0f/r;
    float x=vx*inv, y=vy*inv, z=vz*inv;
    d_Y[e*8+0]=S3f*y;  d_Y[e*8+1]=S3f*z;  d_Y[e*8+2]=S3f*x;
    d_Y[e*8+3]=S15f*x*y; d_Y[e*8+4]=S15f*y*z;
    d_Y[e*8+5]=0.5f*S5f*(3.f*z*z-1.f);
    d_Y[e*8+6]=S15f*x*z; d_Y[e*8+7]=0.5f*S15f*(x*x-y*y);
}

// ------------------------- LUT build: dual-number MLP -----------------------
#define MM64(DST,SRC) do{ \
    _Pragma("unroll") for(int i=0;i<8;i++) DST[i]=0.f; \
    _Pragma("unroll") for(int k0=0;k0<64;k0+=4){ \
        _Pragma("unroll") for(int i=0;i<8;i++){ \
            float4 a4=*(const float4*)&SRC[r0+i][k0]; \
            DST[i]=fmaf(a4.x,wc[k0],DST[i]); DST[i]=fmaf(a4.y,wc[k0+1],DST[i]); \
            DST[i]=fmaf(a4.z,wc[k0+2],DST[i]); DST[i]=fmaf(a4.w,wc[k0+3],DST[i]); } } \
}while(0)
#define FILLW() _Pragma("unroll") for(int k=0;k<64;k++) wc[k]=sW[k*65+j]

__global__ void __launch_bounds__(256) k_lut_build(const float* __restrict__ w1,
        const float* __restrict__ w2, const float* __restrict__ w3,
        const float* __restrict__ w4, int w4s, int cb1, int cb2, int which){
    __shared__ float sV[32][64];
    __shared__ float sT[32][64];
    __shared__ float sW[64*65];
    int tid=threadIdx.x, j=tid&63, r0=(tid>>6)*8;
    int row0=blockIdx.x*32;
    float* LR = which? d_lutR1 : d_lutR0;
    float* LD = which? d_lutD1 : d_lutD0;
    // fill feat + dfeat for 32 rows: thread (rr=tid>>3, q=tid&7)
    {
        int rr=tid>>3, q=tid&7;
        float rv = (float)(row0+rr)*LUT_H;
        float rs = fmaxf(rv, 1e-6f);
        float inv = 1.0f/rs;
        float uu = rs*0.2f;
        float u2=uu*uu, u4=u2*u2, u5=u4*uu, u6=u5*uu, u7=u6*uu;
        float fc  = 1.f - 21.f*u5 + 35.f*u6 - 15.f*u7;
        float dfc = (-105.f*u4 + 210.f*u5 - 105.f*u6)*0.2f;
        if (uu >= 1.0f){ fc=0.f; dfc=0.f; }
        float a = (float)(q+1)*(PIf/5.0f);
        float sa=sinf(a*rs), ca=cosf(a*rs);
        float c0 = sqrtf(0.4f);
        sV[rr][q] = c0*sa*inv*fc;
        sT[rr][q] = c0*((a*ca*inv - sa*inv*inv)*fc + sa*inv*dfc);
    }
    __syncthreads();
    float aV[8], aT[8], wc[64];
    // layer 1: 8 -> 64
    #pragma unroll
    for (int i=0;i<8;i++){ aV[i]=0.f; aT[i]=0.f; }
    #pragma unroll
    for (int k=0;k<8;k++){
        float w=w1[k*64+j];
        #pragma unroll
        for (int i=0;i<8;i++){ aV[i]=fmaf(sV[r0+i][k],w,aV[i]); aT[i]=fmaf(sT[r0+i][k],w,aT[i]); }
    }
    __syncthreads();
    #pragma unroll
    for (int i=0;i<8;i++){ float z=aV[i]; sV[r0+i][j]=siluf(z); sT[r0+i][j]=dsiluf(z)*aT[i]; }
    for(int idx=tid; idx<4096; idx+=256){ int a_=idx>>6, b_=idx&63; sW[a_*65+b_]=w2[idx]; }
    __syncthreads();
    FILLW();
    MM64(aV, sV);
    MM64(aT, sT);
    __syncthreads();
    #pragma unroll
    for (int i=0;i<8;i++){ float z=aV[i]; sV[r0+i][j]=siluf(z); sT[r0+i][j]=dsiluf(z)*aT[i]; }
    for(int idx=tid; idx<4096; idx+=256){ int a_=idx>>6, b_=idx&63; sW[a_*65+b_]=w3[idx]; }
    __syncthreads();
    FILLW();
    MM64(aV, sV);
    MM64(aT, sT);
    __syncthreads();
    #pragma unroll
    for (int i=0;i<8;i++){ float z=aV[i]; sV[r0+i][j]=siluf(z); sT[r0+i][j]=dsiluf(z)*aT[i]; }
    int cbs[3]={0,cb1,cb2};
    for (int p=0;p<3;p++){
        for(int idx=tid; idx<4096; idx+=256){ int a_=idx>>6, b_=idx&63; sW[a_*65+b_]=w4[a_*w4s+cbs[p]+b_]; }
        __syncthreads();
        FILLW();
        MM64(aV, sV);
        MM64(aT, sT);
        #pragma unroll
        for (int i=0;i<8;i++){
            LR[(row0+r0+i)*192 + p*64 + j] = aV[i];
            LD[(row0+r0+i)*192 + p*64 + j] = aT[i];
        }
        __syncthreads();
    }
}

// ---------------------- per-edge LUT interpolation --------------------------
__global__ void __launch_bounds__(256) k_interp(){
    int tid=threadIdx.x;
    int c=tid&63;
    int e=blockIdx.x*4+(tid>>6);
    float r = d_r[e];
    if (r >= 5.0f){
        #pragma unroll
        for (int p=0;p<3;p++){ d_R0[e*192+p*64+c]=0.f; d_R1[e*192+p*64+c]=0.f; }
        return;
    }
    float u = r*LUT_INV;
    int i = (int)u; if (i > NLUT-2) i = NLUT-2;
    float w = u - (float)i;
    const float* A0 = d_lutR0 + i*192;
    const float* A1 = d_lutR1 + i*192;
    #pragma unroll
    for (int p=0;p<3;p++){
        int off=p*64+c;
        float v0=A0[off], v1=A0[192+off];
        d_R0[e*192+off] = v0 + w*(v1-v0);
        float q0=A1[off], q1=A1[192+off];
        d_R1[e*192+off] = q0 + w*(q1-q0);
    }
}

// ----------------------------------------------------------------------------
__global__ void k_node_init(const float* __restrict__ attrs, const float* __restrict__ w_emb,
                            const float* __restrict__ w_up0, const float* __restrict__ aener,
                            const int* __restrict__ batch){
    int n = blockIdx.x, c = threadIdx.x;
    __shared__ int ssp;
    __shared__ float sh0[64];
    if (c==0){
        int sp=0;
        for (int q=0;q<10;q++) if (attrs[n*10+q] > 0.5f) sp=q;
        ssp=sp; d_sp[n]=sp;
        atomicAdd(&d_e[batch[n]], aener[sp]);
    }
    __syncthreads();
    sh0[c]=w_emb[ssp*64+c];
    __syncthreads();
    float a=0.f;
    for (int k=0;k<64;k++) a = fmaf(sh0[k], w_up0[k*64+c], a);
    d_hup0[n*64+c]=a;
}

// ----------------------------------------------------------------------------
__global__ void k_int0_agg(const int* __restrict__ ei){
    int n = blockIdx.x, c = threadIdx.x;
    int b0=d_off_r[n], b1=d_off_r[n+1];
    float a0=0.f, a1[3]={0,0,0}, a2[5]={0,0,0,0,0};
    for (int q=b0;q<b1;q++){
        int e=d_csr_r[q]; int s=ei[e];
        float hup=d_hup0[s*64+c];
        const float* Rb=d_R0+e*192;
        const float* Ye=d_Y+e*8;
        a0 = fmaf(hup*K0C, Rb[c], a0);
        float m1=hup*Rb[64+c]*K1C;
        #pragma unroll
        for (int i=0;i<3;i++) a1[i]=fmaf(m1,Ye[i],a1[i]);
        float m2=hup*Rb[128+c]*K2C;
        #pragma unroll
        for (int i=0;i<5;i++) a2[i]=fmaf(m2,Ye[3+i],a2[i]);
    }
    d_agg0_0[n*64+c]=a0;
    #pragma unroll
    for (int i=0;i<3;i++) d_agg0_1[(n*64+c)*3+i]=a1[i];
    #pragma unroll
    for (int i=0;i<5;i++) d_agg0_2[(n*64+c)*5+i]=a2[i];
}

// ----------------------------------------------------------------------------
__global__ void k_int0_node(const float* __restrict__ w_emb, const float* __restrict__ w_out0,
                            const float* __restrict__ w_sc0, const float* __restrict__ w_r0,
                            const float* __restrict__ w_up1, const int* __restrict__ batch){
    int n=blockIdx.x, tx=threadIdx.x;
    __shared__ float sA0[64], sA1[192], sA2[320], sh0[64], sh1[64];
    __shared__ float sred[2];
    int sp = d_sp[n];
    sA0[tx]=d_agg0_0[n*64+tx];
    sh0[tx]=w_emb[sp*64+tx];
    for (int i=tx;i<192;i+=64) sA1[i]=d_agg0_1[n*192+i];
    for (int i=tx;i<320;i+=64) sA2[i]=d_agg0_2[n*320+i];
    __syncthreads();
    const float* wsc = w_sc0 + sp*4096;
    float acc=0.f;
    for (int c=0;c<64;c++){
        acc = fmaf(sA0[c], w_out0[c*64+tx], acc);
        acc = fmaf(sh0[c], wsc[c*64+tx], acc);
    }
    d_h1_0[n*64+tx]=acc;
    sh1[tx]=acc;
    float ev = acc*w_r0[tx];
    #pragma unroll
    for (int off=16;off>0;off>>=1) ev += __shfl_xor_sync(0xffffffffu, ev, off);
    if ((tx&31)==0) sred[tx>>5]=ev;
    __syncthreads();
    if (tx==0) atomicAdd(&d_e[16+batch[n]], sred[0]+sred[1]);
    float a=0.f;
    for (int c=0;c<64;c++) a = fmaf(sh1[c], w_up1[c*64+tx], a);
    d_hup1_0[n*64+tx]=a;
    float b0=0.f,b1=0.f,b2=0.f;
    for (int c=0;c<64;c++){
        float w = d_W01[c*64+tx];
        b0=fmaf(sA1[c*3+0],w,b0); b1=fmaf(sA1[c*3+1],w,b1); b2=fmaf(sA1[c*3+2],w,b2);
    }
    float* h1 = d_hup1_1 + (n*64+tx)*3;
    h1[0]=b0; h1[1]=b1; h1[2]=b2;
    float e0_=0.f,e1_=0.f,e2_=0.f,e3_=0.f,e4_=0.f;
    for (int c=0;c<64;c++){
        float w = d_W02[c*64+tx];
        e0_=fmaf(sA2[c*5+0],w,e0_); e1_=fmaf(sA2[c*5+1],w,e1_);
        e2_=fmaf(sA2[c*5+2],w,e2_); e3_=fmaf(sA2[c*5+3],w,e3_);
        e4_=fmaf(sA2[c*5+4],w,e4_);
    }
    float* h2 = d_hup1_2 + (n*64+tx)*5;
    h2[0]=e0_; h2[1]=e1_; h2[2]=e2_; h2[3]=e3_; h2[4]=e4_;
}

// ----------------------------------------------------------------------------
__global__ void k_int1_agg(const int* __restrict__ ei){
    int n = blockIdx.x, c = threadIdx.x;
    int b0=d_off_r[n], b1=d_off_r[n+1];
    float a0=0.f, a1=0.f, a2=0.f;
    for (int q=b0;q<b1;q++){
        int e=d_csr_r[q]; int s=ei[e];
        const float* Rb=d_R1+e*192;
        const float* Ye=d_Y+e*8;
        a0 = fmaf(d_hup1_0[s*64+c]*K0C, Rb[c], a0);
        const float* hv1 = d_hup1_1 + (s*64+c)*3;
        float S1 = Ye[0]*hv1[0]+Ye[1]*hv1[1]+Ye[2]*hv1[2];
        a1 = fmaf(S1*K4N, Rb[64+c], a1);
        const float* hv2 = d_hup1_2 + (s*64+c)*5;
        float S2 = Ye[3]*hv2[0]+Ye[4]*hv2[1]+Ye[5]*hv2[2]+Ye[6]*hv2[3]+Ye[7]*hv2[4];
        a2 = fmaf(S2*K9N, Rb[128+c], a2);
    }
    d_agg1[n*64+c]=a0;
    d_agg1[N64+n*64+c]=a1;
    d_agg1[2*N64+n*64+c]=a2;
}

// ----------------------------------------------------------------------------
__global__ void k_int1_node(const float* __restrict__ w_out1, const float* __restrict__ w_sc1,
                            const float* __restrict__ w_m1, const float* __restrict__ w_m2,
                            const float* __restrict__ w_r0, const int* __restrict__ batch){
    int n=blockIdx.x, tx=threadIdx.x;
    __shared__ float sA0[64], sA1[64], sA2[64], sh1[64], sh2[64], sg2[64];
    __shared__ float sv[16], sdz[16];
    int sp=d_sp[n];
    sA0[tx]=d_agg1[n*64+tx];
    sA1[tx]=d_agg1[N64+n*64+tx];
    sA2[tx]=d_agg1[2*N64+n*64+tx];
    sh1[tx]=d_h1_0[n*64+tx];
    __syncthreads();
    const float* wo0 = w_out1;
    const float* wo4 = w_out1 + 4*4096;
    const float* wo9 = w_out1 + 9*4096;
    const float* wsc = w_sc1 + sp*4096;
    float h2=0.f;
    for (int c=0;c<64;c++){
        h2 = fmaf(sA0[c], wo0[c*64+tx], h2);
        h2 = fmaf(sA1[c], wo4[c*64+tx], h2);
        h2 = fmaf(sA2[c], wo9[c*64+tx], h2);
        h2 = fmaf(sh1[c], wsc[c*64+tx], h2);
    }
    sh2[tx]=h2;
    __syncthreads();
    if (tx < 16){
        float z=0.f;
        for (int d=0;d<64;d++) z = fmaf(sh2[d], w_m1[d*16+tx], z);
        float s=1.f/(1.f+expf(-z));
        sv[tx]  = z*s*w_m2[tx];
        sdz[tx] = s*(1.f+z*(1.f-s))*w_m2[tx];
    }
    __syncthreads();
    if (tx==0){
        float t=0.f;
        for (int q=0;q<16;q++) t+=sv[q];
        atomicAdd(&d_e[32+batch[n]], t);
    }
    float gh2=0.f;
    #pragma unroll
    for (int q=0;q<16;q++) gh2 = fmaf(w_m1[tx*16+q], sdz[q], gh2);
    sg2[tx]=gh2;
    __syncthreads();
    float ga0=0.f, ga1=0.f, ga2=0.f, gh1=w_r0[tx];
    for (int d=0;d<64;d++){
        float g = sg2[d];
        ga0 = fmaf(wo0[tx*64+d], g, ga0);
        ga1 = fmaf(wo4[tx*64+d], g, ga1);
        ga2 = fmaf(wo9[tx*64+d], g, ga2);
        gh1 = fmaf(wsc[tx*64+d], g, gh1);
    }
    d_gagg1[n*64+tx]=ga0;
    d_gagg1[N64+n*64+tx]=ga1;
    d_gagg1[2*N64+n*64+tx]=ga2;
    d_gh1_0[n*64+tx]=gh1;
}

// ----------------------------------------------------------------------------
__global__ void k_int1_bwd_send(const int* __restrict__ ei){
    int n = blockIdx.x, c = threadIdx.x;
    int b0=d_off_s[n], b1=d_off_s[n+1];
    float g0a=0.f, g1a[3]={0,0,0}, g2a[5]={0,0,0,0,0};
    for (int q=b0;q<b1;q++){
        int e=d_csr_s[q]; int t=ei[NE+e];
        float g0=d_gagg1[t*64+c];
        float g1=d_gagg1[N64+t*64+c];
        float g2=d_gagg1[2*N64+t*64+c];
        const float* Rb=d_R1+e*192;
        const float* Ye=d_Y+e*8;
        g0a = fmaf(K0C*Rb[c], g0, g0a);
        float a1=K4N*Rb[64+c]*g1;
        #pragma unroll
        for (int i=0;i<3;i++) g1a[i]=fmaf(a1,Ye[i],g1a[i]);
        float a2=K9N*Rb[128+c]*g2;
        #pragma unroll
        for (int i=0;i<5;i++) g2a[i]=fmaf(a2,Ye[3+i],g2a[i]);
    }
    d_gHup1_0[n*64+c]=g0a;
    #pragma unroll
    for (int i=0;i<3;i++) d_gHup1_1[(n*64+c)*3+i]=g1a[i];
    #pragma unroll
    for (int i=0;i<5;i++) d_gHup1_2[(n*64+c)*5+i]=g2a[i];
}

// ----------------------------------------------------------------------------
__global__ void k_int1_bwd_edge(const int* __restrict__ ei){
    int gtid = blockIdx.x*blockDim.x + threadIdx.x;
    int e = gtid>>5, lane = gtid&31;
    int s = ei[e], t = ei[NE+e];
    float y[8];
    #pragma unroll
    for (int i=0;i<8;i++) y[i]=d_Y[e*8+i];
    float tY[8]={0,0,0,0,0,0,0,0};
    #pragma unroll
    for (int h=0;h<2;h++){
        int c = lane + 32*h;
        float g0 = d_gagg1[t*64+c];
        float g1 = d_gagg1[N64+t*64+c];
        float g2 = d_gagg1[2*N64+t*64+c];
        float r1 = d_R1[e*192+64+c], r2 = d_R1[e*192+128+c];
        float h0v = d_hup1_0[s*64+c];
        const float* h1v = d_hup1_1 + (s*64+c)*3;
        const float* h2v = d_hup1_2 + (s*64+c)*5;
        float s1 = y[0]*h1v[0]+y[1]*h1v[1]+y[2]*h1v[2];
        float s2 = y[3]*h2v[0]+y[4]*h2v[1]+y[5]*h2v[2]+y[6]*h2v[3]+y[7]*h2v[4];
        d_R1[e*192+c]     = K0C*h0v*g0;
        d_R1[e*192+64+c]  = K4N*s1*g1;
        d_R1[e*192+128+c] = K9N*s2*g2;
        float a1 = K4N*r1*g1;
        float a2 = K9N*r2*g2;
        #pragma unroll
        for (int i=0;i<3;i++) tY[i]   = fmaf(a1,h1v[i],tY[i]);
        #pragma unroll
        for (int i=0;i<5;i++) tY[3+i] = fmaf(a2,h2v[i],tY[3+i]);
    }
    #pragma unroll
    for (int i=0;i<8;i++){
        float v=tY[i];
        #pragma unroll
        for (int off=16;off>0;off>>=1) v += __shfl_xor_sync(0xffffffffu, v, off);
        tY[i]=v;
    }
    if (lane==0){
        #pragma unroll
        for (int i=0;i<8;i++) d_gY[e*8+i]=tY[i];
    }
}

// ----------------------------------------------------------------------------
__global__ void k_int1_bwd_node(const float* __restrict__ w_up1, const float* __restrict__ w_out0){
    int n=blockIdx.x, tx=threadIdx.x;
    __shared__ float sg0[64], sgh1[64], sg1[192], sg2[320];
    sg0[tx]=d_gHup1_0[n*64+tx];
    for (int i=tx;i<192;i+=64) sg1[i]=d_gHup1_1[n*192+i];
    for (int i=tx;i<320;i+=64) sg2[i]=d_gHup1_2[n*320+i];
    __syncthreads();
    float gh1 = d_gh1_0[n*64+tx];
    for (int d=0;d<64;d++) gh1 = fmaf(sg0[d], w_up1[tx*64+d], gh1);
    sgh1[tx]=gh1;
    __syncthreads();
    float ga=0.f;
    for (int d=0;d<64;d++) ga = fmaf(w_out0[tx*64+d], sgh1[d], ga);
    d_gagg0_0[n*64+tx]=ga;
    float b0=0.f,b1=0.f,b2=0.f;
    for (int d=0;d<64;d++){
        float w = d_W01[tx*64+d];
        b0=fmaf(sg1[d*3+0],w,b0); b1=fmaf(sg1[d*3+1],w,b1); b2=fmaf(sg1[d*3+2],w,b2);
    }
    float* o1 = d_gagg0_1 + (n*64+tx)*3;
    o1[0]=b0; o1[1]=b1; o1[2]=b2;
    float c0=0.f,c1=0.f,c2=0.f,c3=0.f,c4=0.f;
    for (int d=0;d<64;d++){
        float w = d_W02[tx*64+d];
        c0=fmaf(sg2[d*5+0],w,c0); c1=fmaf(sg2[d*5+1],w,c1);
        c2=fmaf(sg2[d*5+2],w,c2); c3=fmaf(sg2[d*5+3],w,c3);
        c4=fmaf(sg2[d*5+4],w,c4);
    }
    float* o2 = d_gagg0_2 + (n*64+tx)*5;
    o2[0]=c0; o2[1]=c1; o2[2]=c2; o2[3]=c3; o2[4]=c4;
}

// ----------------------------------------------------------------------------
__global__ void k_int0_bwd_edge(const int* __restrict__ ei){
    int gtid = blockIdx.x*blockDim.x + threadIdx.x;
    int e = gtid>>5, lane = gtid&31;
    int s = ei[e], t = ei[NE+e];
    float y[8];
    #pragma unroll
    for (int i=0;i<8;i++) y[i]=d_Y[e*8+i];
    float tY[8]={0,0,0,0,0,0,0,0};
    #pragma unroll
    for (int h=0;h<2;h++){
        int c = lane + 32*h;
        float hp = d_hup0[s*64+c];
        float ga0 = d_gagg0_0[t*64+c];
        const float* ga1 = d_gagg0_1 + (t*64+c)*3;
        const float* ga2 = d_gagg0_2 + (t*64+c)*5;
        float r1 = d_R0[e*192+64+c], r2 = d_R0[e*192+128+c];
        float s1 = y[0]*ga1[0]+y[1]*ga1[1]+y[2]*ga1[2];
        float s2 = y[3]*ga2[0]+y[4]*ga2[1]+y[5]*ga2[2]+y[6]*ga2[3]+y[7]*ga2[4];
        d_R0[e*192+c]     = K0C*hp*ga0;
        d_R0[e*192+64+c]  = K1C*hp*s1;
        d_R0[e*192+128+c] = K2C*hp*s2;
        float b1 = K1C*hp*r1;
        float b2 = K2C*hp*r2;
        #pragma unroll
        for (int i=0;i<3;i++) tY[i]   = fmaf(b1, ga1[i], tY[i]);
        #pragma unroll
        for (int i=0;i<5;i++) tY[3+i] = fmaf(b2, ga2[i], tY[3+i]);
    }
    #pragma unroll
    for (int i=0;i<8;i++){
        float v=tY[i];
        #pragma unroll
        for (int off=16;off>0;off>>=1) v += __shfl_xor_sync(0xffffffffu, v, off);
        tY[i]=v;
    }
    if (lane==0){
        #pragma unroll
        for (int i=0;i<8;i++) d_gY[e*8+i] += tY[i];
    }
}

// ---------------------- gr = <F'(r), gR> via LUT -----------------------------
__global__ void __launch_bounds__(256) k_force_dot(){
    __shared__ float sred[4][2];
    int tid=threadIdx.x;
    int c=tid&63, sub=tid>>6;
    int e=blockIdx.x*4+sub;
    float r = d_r[e];
    float part = 0.f;
    if (r < 5.0f){
        float u = r*LUT_INV;
        int i = (int)u; if (i > NLUT-2) i = NLUT-2;
        float w = u - (float)i;
        const float* D0 = d_lutD0 + i*192;
        const float* D1 = d_lutD1 + i*192;
        #pragma unroll
        for (int p=0;p<3;p++){
            int off=p*64+c;
            float v0=D0[off], v1=D0[192+off];
            part = fmaf(v0 + w*(v1-v0), d_R0[e*192+off], part);
            float q0=D1[off], q1=D1[192+off];
            part = fmaf(q0 + w*(q1-q0), d_R1[e*192+off], part);
        }
    }
    #pragma unroll
    for (int off=16;off>0;off>>=1) part += __shfl_xor_sync(0xffffffffu, part, off);
    if ((tid&31)==0) sred[sub][(tid>>5)&1]=part;
    __syncthreads();
    if (c==0) d_gr[e] = sred[sub][0]+sred[sub][1];
}

// ----------------------------------------------------------------------------
__global__ void k_force_edge(){
    int e = blockIdx.x*blockDim.x + threadIdx.x;
    if (e >= NE) return;
    float vx=d_vec[e*3+0], vy=d_vec[e*3+1], vz=d_vec[e*3+2];
    float r = d_r[e], inv = 1.0f/r;
    float x=vx*inv, y=vy*inv, z=vz*inv;
    const float* gy = d_gY + e*8;
    float gux = S3f*gy[2] + S15f*(y*gy[3] + z*gy[6] + x*gy[7]);
    float guy = S3f*gy[0] + S15f*(x*gy[3] + z*gy[4] - y*gy[7]);
    float guz = S3f*gy[1] + S15f*(y*gy[4] + x*gy[6]) + 3.f*S5f*z*gy[5];
    float gr = d_gr[e];
    float dot = x*gux + y*guy + z*guz;
    d_gvec[e*3+0] = (gux - x*dot)*inv + gr*x;
    d_gvec[e*3+1] = (guy - y*dot)*inv + gr*y;
    d_gvec[e*3+2] = (guz - z*dot)*inv + gr*z;
}

// ----------------------------------------------------------------------------
__global__ void k_force_node(float* __restrict__ out){
    int n = blockIdx.x*4 + (threadIdx.x>>5);
    int lane = threadIdx.x&31;
    float fx=0.f, fy=0.f, fz=0.f;
    int b0=d_off_r[n], b1=d_off_r[n+1];
    for (int q=b0+lane;q<b1;q+=32){
        int e=d_csr_r[q];
        fx-=d_gvec[e*3+0]; fy-=d_gvec[e*3+1]; fz-=d_gvec[e*3+2];
    }
    b0=d_off_s[n]; b1=d_off_s[n+1];
    for (int q=b0+lane;q<b1;q+=32){
        int e=d_csr_s[q];
        fx+=d_gvec[e*3+0]; fy+=d_gvec[e*3+1]; fz+=d_gvec[e*3+2];
    }
    #pragma unroll
    for (int off=16;off>0;off>>=1){
        fx+=__shfl_xor_sync(0xffffffffu,fx,off);
        fy+=__shfl_xor_sync(0xffffffffu,fy,off);
        fz+=__shfl_xor_sync(0xffffffffu,fz,off);
    }
    if (lane==0){
        float* F = out + 64;
        F[n*3+0]=fx; F[n*3+1]=fy; F[n*3+2]=fz;
    }
}

// ----------------------------------------------------------------------------
__global__ void k_finalize(float* __restrict__ out){
    int g = threadIdx.x;
    if (g >= 16) return;
    float e0=d_e[g], e1=d_e[16+g], e2=d_e[32+g];
    out[g] = e0+e1+e2;
    out[16+g*3+0]=e0; out[16+g*3+1]=e1; out[16+g*3+2]=e2;
}

// ----------------------------------------------------------------------------
extern "C" void kernel_launch(void* const* d_in, const int* in_sizes, int n_in,
                              void* d_out, int out_size){
    const float* pos    = (const float*)d_in[0];
    const float* attrs  = (const float*)d_in[1];
    const float* shifts = (const float*)d_in[2];
    const float* aener  = (const float*)d_in[3];
    const float* w_emb  = (const float*)d_in[4];
    const float* w_up0  = (const float*)d_in[5];
    const float* r0w1   = (const float*)d_in[6];
    const float* r0w2   = (const float*)d_in[7];
    const float* r0w3   = (const float*)d_in[8];
    const float* r0w4   = (const float*)d_in[9];
    const float* w_out0 = (const float*)d_in[10];
    const float* w_sc0  = (const float*)d_in[11];
    const float* w_r0   = (const float*)d_in[12];
    const float* w_up1  = (const float*)d_in[13];
    const float* r1w1   = (const float*)d_in[14];
    const float* r1w2   = (const float*)d_in[15];
    const float* r1w3   = (const float*)d_in[16];
    const float* r1w4   = (const float*)d_in[17];
    const float* w_out1 = (const float*)d_in[18];
    const float* w_sc1  = (const float*)d_in[19];
    const float* w_m1   = (const float*)d_in[20];
    const float* w_m2   = (const float*)d_in[21];
    const int*   ei     = (const int*)d_in[22];
    const int*   batch  = (const int*)d_in[23];
    float* out = (float*)d_out;

    k_zero<<<64,256>>>();
    k_hist<<<625,256>>>(ei);
    k_scan<<<1,1024>>>();
    k_csr_fill<<<625,256>>>(ei);
    k_precW<<<dim3(64,2),64>>>(w_out0, w_up1);
    k_lut_build<<<NLUT/32,256>>>(r0w1,r0w2,r0w3,r0w4, 192, 64, 128, 0);
    k_lut_build<<<NLUT/32,256>>>(r1w1,r1w2,r1w3,r1w4, 832, 256, 576, 1);
    k_edge_geom<<<625,256>>>(pos, shifts, ei);
    k_interp<<<NE/4,256>>>();
    k_node_init<<<NN,64>>>(attrs, w_emb, w_up0, aener, batch);
    k_int0_agg<<<NN,64>>>(ei);
    k_int0_node<<<NN,64>>>(w_emb, w_out0, w_sc0, w_r0, w_up1, batch);
    k_int1_agg<<<NN,64>>>(ei);
    k_int1_node<<<NN,64>>>(w_out1, w_sc1, w_m1, w_m2, w_r0, batch);
    k_int1_bwd_send<<<NN,64>>>(ei);
    k_int1_bwd_edge<<<NE*32/256,256>>>(ei);
    k_int1_bwd_node<<<NN,64>>>(w_up1, w_out0);
    k_int0_bwd_edge<<<NE*32/256,256>>>(ei);
    k_force_dot<<<NE/4,256>>>();
    k_force_edge<<<625,256>>>();
    k_force_node<<<NN/4,128>>>(out);
    k_finalize<<<1,16>>>(out);
}

// round 6
// speedup vs baseline: 2.7887x; 1.1599x over previous
#include <cuda_runtime.h>
#include <math.h>

#define NE 160000
#define NN 10000
#define N64 (NN*64)
#define NLUT 8192
#define LUT_H   (5.0f/(NLUT-1))
#define LUT_INV ((NLUT-1)/5.0f)

#define S3f  1.7320508075688772f
#define S5f  2.2360679774997896f
#define S15f 3.8729833462074170f
#define PIf  3.14159265358979323846f
#define K0C  (0.0625f)
#define K1C  (0.0625f/S3f)
#define K2C  (0.0625f/S5f)
#define K4N  (-0.0625f/S3f)
#define K9N  (0.0625f/S5f)

// ---------------- scratch ----------------
__device__ float d_vec[NE*3];
__device__ float d_r[NE];
__device__ float d_Y[NE*8];
__device__ float d_gY[NE*8];
__device__ float d_gvec[NE*3];
__device__ float d_gr[NE];

__device__ float d_lutR0[NLUT*192], d_lutD0[NLUT*192];
__device__ float d_lutR1[NLUT*192], d_lutD1[NLUT*192];

__device__ int   d_sp[NN];
__device__ float d_hup0[N64];
__device__ float d_h1_0[N64];
__device__ float d_hup1_0[N64];
__device__ float d_hup1_1[3*N64];   // plane layout [i][N64]
__device__ float d_hup1_2[5*N64];
__device__ float d_gagg1[3*N64];
__device__ float d_gh1_0[N64];
__device__ float d_gagg0_0[N64];
__device__ float d_gagg0_1[3*N64];  // planes
__device__ float d_gagg0_2[5*N64];
__device__ float d_W01[4096], d_W02[4096];
__device__ float d_e[48];

// CSR
__device__ int d_deg_r[NN], d_deg_s[NN];
__device__ int d_off_r[NN+1], d_off_s[NN+1];
__device__ int d_cur_r[NN], d_cur_s[NN];
__device__ int d_csr_r[NE], d_csr_s[NE];

__device__ __forceinline__ float siluf(float x){ float s=1.f/(1.f+expf(-x)); return x*s; }
__device__ __forceinline__ float dsiluf(float x){ float s=1.f/(1.f+expf(-x)); return s*(1.f+x*(1.f-s)); }
__device__ __forceinline__ float lerpf(const float* A, int off, float w){
    float v0=A[off]; return fmaf(w, A[192+off]-v0, v0);
}
__device__ __forceinline__ void lut_idx(float r, int& li, float& w){
    float u = fminf(r*LUT_INV, (float)(NLUT-1));
    li = (int)u; if (li > NLUT-2) li = NLUT-2;
    w = u - (float)li;
}

// ----------------------------------------------------------------------------
__global__ void k_zero(){
    int i = blockIdx.x*blockDim.x + threadIdx.x;
    int st = gridDim.x*blockDim.x;
    for (int j=i;j<48;j+=st) d_e[j]=0.f;
    for (int j=i;j<NN;j+=st){ d_deg_r[j]=0; d_deg_s[j]=0; }
}

__global__ void k_hist(const int* __restrict__ ei){
    int e = blockIdx.x*blockDim.x + threadIdx.x;
    atomicAdd(&d_deg_r[ei[NE+e]],1);
    atomicAdd(&d_deg_s[ei[e]],1);
}

__global__ void k_scan(){
    __shared__ int sh[1024];
    int t = threadIdx.x;
    for (int w=0; w<2; w++){
        int* deg = w? d_deg_s: d_deg_r;
        int* off = w? d_off_s: d_off_r;
        int* cur = w? d_cur_s: d_cur_r;
        int base = t*10, s=0;
        #pragma unroll
        for (int i=0;i<10;i++){ int idx=base+i; if (idx<NN) s+=deg[idx]; }
        sh[t]=s;
        __syncthreads();
        for (int d=1; d<1024; d<<=1){
            int v = (t>=d)? sh[t-d]:0;
            __syncthreads();
            sh[t]+=v;
            __syncthreads();
        }
        int run = sh[t]-s;
        #pragma unroll
        for (int i=0;i<10;i++){ int idx=base+i; if (idx<NN){ off[idx]=run; cur[idx]=run; run+=deg[idx]; } }
        if (t==0) off[NN]=NE;
        __syncthreads();
    }
}

__global__ void k_csr_fill(const int* __restrict__ ei){
    int e = blockIdx.x*blockDim.x + threadIdx.x;
    int p = atomicAdd(&d_cur_r[ei[NE+e]],1); d_csr_r[p]=e;
    int q = atomicAdd(&d_cur_s[ei[e]],1);    d_csr_s[q]=e;
}

// ----------------------------------------------------------------------------
__global__ void k_precW(const float* __restrict__ w_out0, const float* __restrict__ w_up1){
    int c = blockIdx.x, l = blockIdx.y+1, d2 = threadIdx.x;
    const float* wo = w_out0 + l*4096;
    const float* wu = w_up1  + l*4096;
    float a=0.f;
    for (int d=0;d<64;d++) a = fmaf(wo[c*64+d], wu[d*64+d2], a);
    if (l==1) d_W01[c*64+d2]=a; else d_W02[c*64+d2]=a;
}

// ----------------------------------------------------------------------------
__global__ void k_edge_geom(const float* __restrict__ pos, const float* __restrict__ shifts,
                            const int* __restrict__ ei){
    int e = blockIdx.x*blockDim.x + threadIdx.x;
    if (e >= NE) return;
    int s = ei[e], t = ei[NE+e];
    float vx = pos[t*3+0]-pos[s*3+0]+shifts[e*3+0];
    float vy = pos[t*3+1]-pos[s*3+1]+shifts[e*3+1];
    float vz = pos[t*3+2]-pos[s*3+2]+shifts[e*3+2];
    float r  = sqrtf(vx*vx+vy*vy+vz*vz + 1e-12f);
    d_vec[e*3+0]=vx; d_vec[e*3+1]=vy; d_vec[e*3+2]=vz; d_r[e]=r;
    float inv = 1.0f/r;
    float x=vx*inv, y=vy*inv, z=vz*inv;
    d_Y[e*8+0]=S3f*y;  d_Y[e*8+1]=S3f*z;  d_Y[e*8+2]=S3f*x;
    d_Y[e*8+3]=S15f*x*y; d_Y[e*8+4]=S15f*y*z;
    d_Y[e*8+5]=0.5f*S5f*(3.f*z*z-1.f);
    d_Y[e*8+6]=S15f*x*z; d_Y[e*8+7]=0.5f*S15f*(x*x-y*y);
}

// ------------------------- LUT build: dual-number MLP (K-baked) --------------
#define MM64(DST,SRC) do{ \
    _Pragma("unroll") for(int i=0;i<8;i++) DST[i]=0.f; \
    _Pragma("unroll") for(int k0=0;k0<64;k0+=4){ \
        _Pragma("unroll") for(int i=0;i<8;i++){ \
            float4 a4=*(const float4*)&SRC[r0+i][k0]; \
            DST[i]=fmaf(a4.x,wc[k0],DST[i]); DST[i]=fmaf(a4.y,wc[k0+1],DST[i]); \
            DST[i]=fmaf(a4.z,wc[k0+2],DST[i]); DST[i]=fmaf(a4.w,wc[k0+3],DST[i]); } } \
}while(0)
#define FILLW() _Pragma("unroll") for(int k=0;k<64;k++) wc[k]=sW[k*65+j]

__global__ void __launch_bounds__(256) k_lut_build(const float* __restrict__ w1,
        const float* __restrict__ w2, const float* __restrict__ w3,
        const float* __restrict__ w4, int w4s, int cb1, int cb2, int which,
        float kp0, float kp1, float kp2){
    __shared__ float sV[32][64];
    __shared__ float sT[32][64];
    __shared__ float sW[64*65];
    int tid=threadIdx.x, j=tid&63, r0=(tid>>6)*8;
    int row0=blockIdx.x*32;
    float* LR = which? d_lutR1 : d_lutR0;
    float* LD = which? d_lutD1 : d_lutD0;
    {
        int rr=tid>>3, q=tid&7;
        float rv = (float)(row0+rr)*LUT_H;
        float rs = fmaxf(rv, 1e-6f);
        float inv = 1.0f/rs;
        float uu = rs*0.2f;
        float u2=uu*uu, u4=u2*u2, u5=u4*uu, u6=u5*uu, u7=u6*uu;
        float fc  = 1.f - 21.f*u5 + 35.f*u6 - 15.f*u7;
        float dfc = (-105.f*u4 + 210.f*u5 - 105.f*u6)*0.2f;
        if (uu >= 1.0f){ fc=0.f; dfc=0.f; }
        float a = (float)(q+1)*(PIf/5.0f);
        float sa=sinf(a*rs), ca=cosf(a*rs);
        float c0 = sqrtf(0.4f);
        sV[rr][q] = c0*sa*inv*fc;
        sT[rr][q] = c0*((a*ca*inv - sa*inv*inv)*fc + sa*inv*dfc);
    }
    __syncthreads();
    float aV[8], aT[8], wc[64];
    #pragma unroll
    for (int i=0;i<8;i++){ aV[i]=0.f; aT[i]=0.f; }
    #pragma unroll
    for (int k=0;k<8;k++){
        float w=w1[k*64+j];
        #pragma unroll
        for (int i=0;i<8;i++){ aV[i]=fmaf(sV[r0+i][k],w,aV[i]); aT[i]=fmaf(sT[r0+i][k],w,aT[i]); }
    }
    __syncthreads();
    #pragma unroll
    for (int i=0;i<8;i++){ float z=aV[i]; sV[r0+i][j]=siluf(z); sT[r0+i][j]=dsiluf(z)*aT[i]; }
    for(int idx=tid; idx<4096; idx+=256){ int a_=idx>>6, b_=idx&63; sW[a_*65+b_]=w2[idx]; }
    __syncthreads();
    FILLW();
    MM64(aV, sV);
    MM64(aT, sT);
    __syncthreads();
    #pragma unroll
    for (int i=0;i<8;i++){ float z=aV[i]; sV[r0+i][j]=siluf(z); sT[r0+i][j]=dsiluf(z)*aT[i]; }
    for(int idx=tid; idx<4096; idx+=256){ int a_=idx>>6, b_=idx&63; sW[a_*65+b_]=w3[idx]; }
    __syncthreads();
    FILLW();
    MM64(aV, sV);
    MM64(aT, sT);
    __syncthreads();
    #pragma unroll
    for (int i=0;i<8;i++){ float z=aV[i]; sV[r0+i][j]=siluf(z); sT[r0+i][j]=dsiluf(z)*aT[i]; }
    int cbs[3]={0,cb1,cb2};
    float kps[3]={kp0,kp1,kp2};
    for (int p=0;p<3;p++){
        for(int idx=tid; idx<4096; idx+=256){ int a_=idx>>6, b_=idx&63; sW[a_*65+b_]=w4[a_*w4s+cbs[p]+b_]; }
        __syncthreads();
        FILLW();
        MM64(aV, sV);
        MM64(aT, sT);
        float kp = kps[p];
        #pragma unroll
        for (int i=0;i<8;i++){
            LR[(row0+r0+i)*192 + p*64 + j] = kp*aV[i];
            LD[(row0+r0+i)*192 + p*64 + j] = kp*aT[i];
        }
        __syncthreads();
    }
}

// ----------------------------------------------------------------------------
__global__ void k_node_init(const float* __restrict__ attrs, const float* __restrict__ w_emb,
                            const float* __restrict__ w_up0, const float* __restrict__ aener,
                            const int* __restrict__ batch){
    int n = blockIdx.x, c = threadIdx.x;
    __shared__ int ssp;
    __shared__ float sh0[64];
    if (c==0){
        int sp=0;
        for (int q=0;q<10;q++) if (attrs[n*10+q] > 0.5f) sp=q;
        ssp=sp; d_sp[n]=sp;
        atomicAdd(&d_e[batch[n]], aener[sp]);
    }
    __syncthreads();
    sh0[c]=w_emb[ssp*64+c];
    __syncthreads();
    float a=0.f;
    for (int k=0;k<64;k++) a = fmaf(sh0[k], w_up0[k*64+c], a);
    d_hup0[n*64+c]=a;
}

// ------------------ interaction 0: fused agg + node mix ----------------------
__global__ void k_int0(const int* __restrict__ ei, const float* __restrict__ w_emb,
                       const float* __restrict__ w_out0, const float* __restrict__ w_sc0,
                       const float* __restrict__ w_r0, const float* __restrict__ w_up1,
                       const int* __restrict__ batch){
    int n=blockIdx.x, tx=threadIdx.x;
    __shared__ float sA0[64], sA1[192], sA2[320], sh0[64], sh1[64];
    __shared__ float sred[2];
    int sp = d_sp[n];
    // agg over incoming edges with inline LUT interp
    float a0=0.f, a1[3]={0,0,0}, a2[5]={0,0,0,0,0};
    int b0=d_off_r[n], b1=d_off_r[n+1];
    for (int q=b0;q<b1;q++){
        int e=d_csr_r[q]; int s=ei[e];
        int li; float w; lut_idx(d_r[e], li, w);
        const float* A = d_lutR0 + li*192;
        float hup=d_hup0[s*64+tx];
        const float* Ye=d_Y+e*8;
        a0 = fmaf(hup, lerpf(A, tx, w), a0);
        float m1 = hup*lerpf(A, 64+tx, w);
        #pragma unroll
        for (int i=0;i<3;i++) a1[i]=fmaf(m1,Ye[i],a1[i]);
        float m2 = hup*lerpf(A, 128+tx, w);
        #pragma unroll
        for (int i=0;i<5;i++) a2[i]=fmaf(m2,Ye[3+i],a2[i]);
    }
    sA0[tx]=a0;
    #pragma unroll
    for (int i=0;i<3;i++) sA1[i*64+tx]=a1[i];
    #pragma unroll
    for (int i=0;i<5;i++) sA2[i*64+tx]=a2[i];
    sh0[tx]=w_emb[sp*64+tx];
    __syncthreads();
    // node mix
    const float* wsc = w_sc0 + sp*4096;
    float acc=0.f;
    for (int c=0;c<64;c++){
        acc = fmaf(sA0[c], w_out0[c*64+tx], acc);
        acc = fmaf(sh0[c], wsc[c*64+tx], acc);
    }
    d_h1_0[n*64+tx]=acc;
    sh1[tx]=acc;
    float ev = acc*w_r0[tx];
    #pragma unroll
    for (int off=16;off>0;off>>=1) ev += __shfl_xor_sync(0xffffffffu, ev, off);
    if ((tx&31)==0) sred[tx>>5]=ev;
    __syncthreads();
    if (tx==0) atomicAdd(&d_e[16+batch[n]], sred[0]+sred[1]);
    float a=0.f;
    for (int c=0;c<64;c++) a = fmaf(sh1[c], w_up1[c*64+tx], a);
    d_hup1_0[n*64+tx]=a;
    float bb[3]={0,0,0};
    for (int c=0;c<64;c++){
        float w = d_W01[c*64+tx];
        #pragma unroll
        for (int i=0;i<3;i++) bb[i]=fmaf(sA1[i*64+c],w,bb[i]);
    }
    #pragma unroll
    for (int i=0;i<3;i++) d_hup1_1[i*N64+n*64+tx]=bb[i];
    float ee[5]={0,0,0,0,0};
    for (int c=0;c<64;c++){
        float w = d_W02[c*64+tx];
        #pragma unroll
        for (int i=0;i<5;i++) ee[i]=fmaf(sA2[i*64+c],w,ee[i]);
    }
    #pragma unroll
    for (int i=0;i<5;i++) d_hup1_2[i*N64+n*64+tx]=ee[i];
}

// ------------------ interaction 1: fused agg + node mix ----------------------
__global__ void k_int1(const int* __restrict__ ei, const float* __restrict__ w_out1,
                       const float* __restrict__ w_sc1, const float* __restrict__ w_m1,
                       const float* __restrict__ w_m2, const float* __restrict__ w_r0,
                       const int* __restrict__ batch){
    int n=blockIdx.x, tx=threadIdx.x;
    __shared__ float sA0[64], sA1[64], sA2[64], sh1[64], sh2[64], sg2[64];
    __shared__ float sv[16], sdz[16];
    int sp=d_sp[n];
    float a0=0.f, a1=0.f, a2=0.f;
    int b0=d_off_r[n], b1=d_off_r[n+1];
    for (int q=b0;q<b1;q++){
        int e=d_csr_r[q]; int s=ei[e];
        int li; float w; lut_idx(d_r[e], li, w);
        const float* A = d_lutR1 + li*192;
        const float* Ye=d_Y+e*8;
        a0 = fmaf(d_hup1_0[s*64+tx], lerpf(A, tx, w), a0);
        float S1=0.f;
        #pragma unroll
        for (int i=0;i<3;i++) S1 = fmaf(Ye[i], d_hup1_1[i*N64+s*64+tx], S1);
        a1 = fmaf(S1, lerpf(A, 64+tx, w), a1);
        float S2=0.f;
        #pragma unroll
        for (int i=0;i<5;i++) S2 = fmaf(Ye[3+i], d_hup1_2[i*N64+s*64+tx], S2);
        a2 = fmaf(S2, lerpf(A, 128+tx, w), a2);
    }
    sA0[tx]=a0; sA1[tx]=a1; sA2[tx]=a2;
    sh1[tx]=d_h1_0[n*64+tx];
    __syncthreads();
    const float* wo0 = w_out1;
    const float* wo4 = w_out1 + 4*4096;
    const float* wo9 = w_out1 + 9*4096;
    const float* wsc = w_sc1 + sp*4096;
    float h2=0.f;
    for (int c=0;c<64;c++){
        h2 = fmaf(sA0[c], wo0[c*64+tx], h2);
        h2 = fmaf(sA1[c], wo4[c*64+tx], h2);
        h2 = fmaf(sA2[c], wo9[c*64+tx], h2);
        h2 = fmaf(sh1[c], wsc[c*64+tx], h2);
    }
    sh2[tx]=h2;
    __syncthreads();
    if (tx < 16){
        float z=0.f;
        for (int d=0;d<64;d++) z = fmaf(sh2[d], w_m1[d*16+tx], z);
        float s=1.f/(1.f+expf(-z));
        sv[tx]  = z*s*w_m2[tx];
        sdz[tx] = s*(1.f+z*(1.f-s))*w_m2[tx];
    }
    __syncthreads();
    if (tx==0){
        float t=0.f;
        for (int q=0;q<16;q++) t+=sv[q];
        atomicAdd(&d_e[32+batch[n]], t);
    }
    float gh2=0.f;
    #pragma unroll
    for (int q=0;q<16;q++) gh2 = fmaf(w_m1[tx*16+q], sdz[q], gh2);
    sg2[tx]=gh2;
    __syncthreads();
    float ga0=0.f, ga1=0.f, ga2=0.f, gh1=w_r0[tx];
    for (int d=0;d<64;d++){
        float g = sg2[d];
        ga0 = fmaf(wo0[tx*64+d], g, ga0);
        ga1 = fmaf(wo4[tx*64+d], g, ga1);
        ga2 = fmaf(wo9[tx*64+d], g, ga2);
        gh1 = fmaf(wsc[tx*64+d], g, gh1);
    }
    d_gagg1[n*64+tx]=ga0;
    d_gagg1[N64+n*64+tx]=ga1;
    d_gagg1[2*N64+n*64+tx]=ga2;
    d_gh1_0[n*64+tx]=gh1;
}

// --------------- int1 backward: fused sender-gather + node mix ---------------
__global__ void k_int1_bwd(const int* __restrict__ ei, const float* __restrict__ w_up1,
                           const float* __restrict__ w_out0){
    int n=blockIdx.x, tx=threadIdx.x;
    __shared__ float sg0[64], sgh1[64], sg1[192], sg2[320];
    float g0a=0.f, g1a[3]={0,0,0}, g2a[5]={0,0,0,0,0};
    int b0=d_off_s[n], b1=d_off_s[n+1];
    for (int q=b0;q<b1;q++){
        int e=d_csr_s[q]; int t=ei[NE+e];
        int li; float w; lut_idx(d_r[e], li, w);
        const float* A = d_lutR1 + li*192;
        const float* Ye=d_Y+e*8;
        float g0=d_gagg1[t*64+tx];
        float g1=d_gagg1[N64+t*64+tx];
        float g2=d_gagg1[2*N64+t*64+tx];
        g0a = fmaf(lerpf(A, tx, w), g0, g0a);
        float aa1 = lerpf(A, 64+tx, w)*g1;
        #pragma unroll
        for (int i=0;i<3;i++) g1a[i]=fmaf(aa1,Ye[i],g1a[i]);
        float aa2 = lerpf(A, 128+tx, w)*g2;
        #pragma unroll
        for (int i=0;i<5;i++) g2a[i]=fmaf(aa2,Ye[3+i],g2a[i]);
    }
    sg0[tx]=g0a;
    #pragma unroll
    for (int i=0;i<3;i++) sg1[i*64+tx]=g1a[i];
    #pragma unroll
    for (int i=0;i<5;i++) sg2[i*64+tx]=g2a[i];
    __syncthreads();
    float gh1 = d_gh1_0[n*64+tx];
    for (int d=0;d<64;d++) gh1 = fmaf(sg0[d], w_up1[tx*64+d], gh1);
    sgh1[tx]=gh1;
    __syncthreads();
    float ga=0.f;
    for (int d=0;d<64;d++) ga = fmaf(w_out0[tx*64+d], sgh1[d], ga);
    d_gagg0_0[n*64+tx]=ga;
    float bb[3]={0,0,0};
    for (int d=0;d<64;d++){
        float w = d_W01[tx*64+d];
        #pragma unroll
        for (int i=0;i<3;i++) bb[i]=fmaf(sg1[i*64+d],w,bb[i]);
    }
    #pragma unroll
    for (int i=0;i<3;i++) d_gagg0_1[i*N64+n*64+tx]=bb[i];
    float cc[5]={0,0,0,0,0};
    for (int d=0;d<64;d++){
        float w = d_W02[tx*64+d];
        #pragma unroll
        for (int i=0;i<5;i++) cc[i]=fmaf(sg2[i*64+d],w,cc[i]);
    }
    #pragma unroll
    for (int i=0;i<5;i++) d_gagg0_2[i*N64+n*64+tx]=cc[i];
}

// --------- int1 backward per-edge: gY + inline <F1', gR1> dot ----------------
__global__ void k_int1_bwd_edge(const int* __restrict__ ei){
    int gtid = blockIdx.x*blockDim.x + threadIdx.x;
    int e = gtid>>5, lane = gtid&31;
    int s = ei[e], t = ei[NE+e];
    int li; float w; lut_idx(d_r[e], li, w);
    const float* A = d_lutR1 + li*192;
    const float* D = d_lutD1 + li*192;
    float y[8];
    #pragma unroll
    for (int i=0;i<8;i++) y[i]=d_Y[e*8+i];
    float tY[8]={0,0,0,0,0,0,0,0};
    float gr=0.f;
    #pragma unroll
    for (int h=0;h<2;h++){
        int c = lane + 32*h;
        float g0 = d_gagg1[t*64+c];
        float g1 = d_gagg1[N64+t*64+c];
        float g2 = d_gagg1[2*N64+t*64+c];
        float h0v = d_hup1_0[s*64+c];
        float h1v[3], h2v[5];
        #pragma unroll
        for (int i=0;i<3;i++) h1v[i]=d_hup1_1[i*N64+s*64+c];
        #pragma unroll
        for (int i=0;i<5;i++) h2v[i]=d_hup1_2[i*N64+s*64+c];
        float s1 = y[0]*h1v[0]+y[1]*h1v[1]+y[2]*h1v[2];
        float s2 = y[3]*h2v[0]+y[4]*h2v[1]+y[5]*h2v[2]+y[6]*h2v[3]+y[7]*h2v[4];
        gr = fmaf(lerpf(D, c, w),      h0v*g0, gr);
        gr = fmaf(lerpf(D, 64+c, w),   s1*g1,  gr);
        gr = fmaf(lerpf(D, 128+c, w),  s2*g2,  gr);
        float a1 = lerpf(A, 64+c, w)*g1;
        float a2 = lerpf(A, 128+c, w)*g2;
        #pragma unroll
        for (int i=0;i<3;i++) tY[i]   = fmaf(a1,h1v[i],tY[i]);
        #pragma unroll
        for (int i=0;i<5;i++) tY[3+i] = fmaf(a2,h2v[i],tY[3+i]);
    }
    #pragma unroll
    for (int i=0;i<8;i++){
        float v=tY[i];
        #pragma unroll
        for (int off=16;off>0;off>>=1) v += __shfl_xor_sync(0xffffffffu, v, off);
        tY[i]=v;
    }
    #pragma unroll
    for (int off=16;off>0;off>>=1) gr += __shfl_xor_sync(0xffffffffu, gr, off);
    if (lane==0){
        #pragma unroll
        for (int i=0;i<8;i++) d_gY[e*8+i]=tY[i];
        d_gr[e]=gr;
    }
}

// --------- int0 backward per-edge + force vector (fused) ---------------------
__global__ void k_int0_bwd_edge(const int* __restrict__ ei){
    int gtid = blockIdx.x*blockDim.x + threadIdx.x;
    int e = gtid>>5, lane = gtid&31;
    int s = ei[e], t = ei[NE+e];
    float r = d_r[e];
    int li; float w; lut_idx(r, li, w);
    const float* A = d_lutR0 + li*192;
    const float* D = d_lutD0 + li*192;
    float y[8];
    #pragma unroll
    for (int i=0;i<8;i++) y[i]=d_Y[e*8+i];
    float tY[8]={0,0,0,0,0,0,0,0};
    float gr=0.f;
    #pragma unroll
    for (int h=0;h<2;h++){
        int c = lane + 32*h;
        float hp = d_hup0[s*64+c];
        float ga0 = d_gagg0_0[t*64+c];
        float ga1[3], ga2[5];
        #pragma unroll
        for (int i=0;i<3;i++) ga1[i]=d_gagg0_1[i*N64+t*64+c];
        #pragma unroll
        for (int i=0;i<5;i++) ga2[i]=d_gagg0_2[i*N64+t*64+c];
        float s1 = y[0]*ga1[0]+y[1]*ga1[1]+y[2]*ga1[2];
        float s2 = y[3]*ga2[0]+y[4]*ga2[1]+y[5]*ga2[2]+y[6]*ga2[3]+y[7]*ga2[4];
        gr = fmaf(lerpf(D, c, w),     hp*ga0, gr);
        gr = fmaf(lerpf(D, 64+c, w),  hp*s1,  gr);
        gr = fmaf(lerpf(D, 128+c, w), hp*s2,  gr);
        float b1 = lerpf(A, 64+c, w)*hp;
        float b2 = lerpf(A, 128+c, w)*hp;
        #pragma unroll
        for (int i=0;i<3;i++) tY[i]   = fmaf(b1, ga1[i], tY[i]);
        #pragma unroll
        for (int i=0;i<5;i++) tY[3+i] = fmaf(b2, ga2[i], tY[3+i]);
    }
    #pragma unroll
    for (int i=0;i<8;i++){
        float v=tY[i];
        #pragma unroll
        for (int off=16;off>0;off>>=1) v += __shfl_xor_sync(0xffffffffu, v, off);
        tY[i]=v;
    }
    #pragma unroll
    for (int off=16;off>0;off>>=1) gr += __shfl_xor_sync(0xffffffffu, gr, off);
    if (lane==0){
        float gy[8];
        #pragma unroll
        for (int i=0;i<8;i++) gy[i]=d_gY[e*8+i]+tY[i];
        float grt = d_gr[e]+gr;
        float vx=d_vec[e*3+0], vy=d_vec[e*3+1], vz=d_vec[e*3+2];
        float inv = 1.0f/r;
        float x=vx*inv, yv=vy*inv, z=vz*inv;
        float gux = S3f*gy[2] + S15f*(yv*gy[3] + z*gy[6] + x*gy[7]);
        float guy = S3f*gy[0] + S15f*(x*gy[3] + z*gy[4] - yv*gy[7]);
        float guz = S3f*gy[1] + S15f*(yv*gy[4] + x*gy[6]) + 3.f*S5f*z*gy[5];
        float dot = x*gux + yv*guy + z*guz;
        d_gvec[e*3+0] = (gux - x*dot)*inv + grt*x;
        d_gvec[e*3+1] = (guy - yv*dot)*inv + grt*yv;
        d_gvec[e*3+2] = (guz - z*dot)*inv + grt*z;
    }
}

// ----------------------------------------------------------------------------
__global__ void k_force_node(float* __restrict__ out){
    int n = blockIdx.x*4 + (threadIdx.x>>5);
    int lane = threadIdx.x&31;
    float fx=0.f, fy=0.f, fz=0.f;
    int b0=d_off_r[n], b1=d_off_r[n+1];
    for (int q=b0+lane;q<b1;q+=32){
        int e=d_csr_r[q];
        fx-=d_gvec[e*3+0]; fy-=d_gvec[e*3+1]; fz-=d_gvec[e*3+2];
    }
    b0=d_off_s[n]; b1=d_off_s[n+1];
    for (int q=b0+lane;q<b1;q+=32){
        int e=d_csr_s[q];
        fx+=d_gvec[e*3+0]; fy+=d_gvec[e*3+1]; fz+=d_gvec[e*3+2];
    }
    #pragma unroll
    for (int off=16;off>0;off>>=1){
        fx+=__shfl_xor_sync(0xffffffffu,fx,off);
        fy+=__shfl_xor_sync(0xffffffffu,fy,off);
        fz+=__shfl_xor_sync(0xffffffffu,fz,off);
    }
    if (lane==0){
        float* F = out + 64;
        F[n*3+0]=fx; F[n*3+1]=fy; F[n*3+2]=fz;
    }
}

// ----------------------------------------------------------------------------
__global__ void k_finalize(float* __restrict__ out){
    int g = threadIdx.x;
    if (g >= 16) return;
    float e0=d_e[g], e1=d_e[16+g], e2=d_e[32+g];
    out[g] = e0+e1+e2;
    out[16+g*3+0]=e0; out[16+g*3+1]=e1; out[16+g*3+2]=e2;
}

// ----------------------------------------------------------------------------
extern "C" void kernel_launch(void* const* d_in, const int* in_sizes, int n_in,
                              void* d_out, int out_size){
    const float* pos    = (const float*)d_in[0];
    const float* attrs  = (const float*)d_in[1];
    const float* shifts = (const float*)d_in[2];
    const float* aener  = (const float*)d_in[3];
    const float* w_emb  = (const float*)d_in[4];
    const float* w_up0  = (const float*)d_in[5];
    const float* r0w1   = (const float*)d_in[6];
    const float* r0w2   = (const float*)d_in[7];
    const float* r0w3   = (const float*)d_in[8];
    const float* r0w4   = (const float*)d_in[9];
    const float* w_out0 = (const float*)d_in[10];
    const float* w_sc0  = (const float*)d_in[11];
    const float* w_r0   = (const float*)d_in[12];
    const float* w_up1  = (const float*)d_in[13];
    const float* r1w1   = (const float*)d_in[14];
    const float* r1w2   = (const float*)d_in[15];
    const float* r1w3   = (const float*)d_in[16];
    const float* r1w4   = (const float*)d_in[17];
    const float* w_out1 = (const float*)d_in[18];
    const float* w_sc1  = (const float*)d_in[19];
    const float* w_m1   = (const float*)d_in[20];
    const float* w_m2   = (const float*)d_in[21];
    const int*   ei     = (const int*)d_in[22];
    const int*   batch  = (const int*)d_in[23];
    float* out = (float*)d_out;

    k_zero<<<64,256>>>();
    k_hist<<<625,256>>>(ei);
    k_scan<<<1,1024>>>();
    k_csr_fill<<<625,256>>>(ei);
    k_precW<<<dim3(64,2),64>>>(w_out0, w_up1);
    k_lut_build<<<NLUT/32,256>>>(r0w1,r0w2,r0w3,r0w4, 192, 64, 128, 0, K0C, K1C, K2C);
    k_lut_build<<<NLUT/32,256>>>(r1w1,r1w2,r1w3,r1w4, 832, 256, 576, 1, K0C, K4N, K9N);
    k_edge_geom<<<625,256>>>(pos, shifts, ei);
    k_node_init<<<NN,64>>>(attrs, w_emb, w_up0, aener, batch);
    k_int0<<<NN,64>>>(ei, w_emb, w_out0, w_sc0, w_r0, w_up1, batch);
    k_int1<<<NN,64>>>(ei, w_out1, w_sc1, w_m1, w_m2, w_r0, batch);
    k_int1_bwd<<<NN,64>>>(ei, w_up1, w_out0);
    k_int1_bwd_edge<<<NE*32/256,256>>>(ei);
    k_int0_bwd_edge<<<NE*32/256,256>>>(ei);
    k_force_node<<<NN/4,128>>>(out);
    k_finalize<<<1,16>>>(out);
}

// round 7
// speedup vs baseline: 2.8264x; 1.0135x over previous
#include <cuda_runtime.h>
#include <math.h>

#define NE 160000
#define NN 10000
#define N64 (NN*64)
#define NLUT 8192
#define LUT_H   (5.0f/(NLUT-1))
#define LUT_INV ((NLUT-1)/5.0f)

#define S3f  1.7320508075688772f
#define S5f  2.2360679774997896f
#define S15f 3.8729833462074170f
#define PIf  3.14159265358979323846f
#define K0C  (0.0625f)
#define K1C  (0.0625f/S3f)
#define K2C  (0.0625f/S5f)
#define K4N  (-0.0625f/S3f)
#define K9N  (0.0625f/S5f)

// ---------------- scratch ----------------
__device__ float d_vec[NE*3];
__device__ float d_r[NE];
__device__ float d_Y[NE*8];
__device__ float d_gvec[NE*3];

__device__ float d_lutR0[NLUT*192], d_lutD0[NLUT*192];
__device__ float d_lutR1[NLUT*192], d_lutD1[NLUT*192];

__device__ int   d_sp[NN];
__device__ float d_hup0[N64];
__device__ float d_h1_0[N64];
__device__ float d_hup1_0[N64];
__device__ float d_hup1_1[3*N64];
__device__ float d_hup1_2[5*N64];
__device__ float d_gagg1[3*N64];
__device__ float d_gh1_0[N64];
__device__ float d_gagg0_0[N64];
__device__ float d_gagg0_1[3*N64];
__device__ float d_gagg0_2[5*N64];
__device__ float d_W01[4096], d_W02[4096];
__device__ float d_e[48];

// CSR
__device__ int d_deg_r[NN], d_deg_s[NN];
__device__ int d_off_r[NN+1], d_off_s[NN+1];
__device__ int d_cur_r[NN], d_cur_s[NN];
__device__ int d_csr_r[NE], d_csr_s[NE];

__device__ __forceinline__ float siluf(float x){ float s=1.f/(1.f+expf(-x)); return x*s; }
__device__ __forceinline__ float dsiluf(float x){ float s=1.f/(1.f+expf(-x)); return s*(1.f+x*(1.f-s)); }
__device__ __forceinline__ float lerpf(const float* A, int off, float w){
    float v0=A[off]; return fmaf(w, A[192+off]-v0, v0);
}
__device__ __forceinline__ void lut_idx(float r, int& li, float& w){
    float u = fminf(r*LUT_INV, (float)(NLUT-1));
    li = (int)u; if (li > NLUT-2) li = NLUT-2;
    w = u - (float)li;
}

// ----------------------------------------------------------------------------
__global__ void k_zero(){
    int i = blockIdx.x*blockDim.x + threadIdx.x;
    int st = gridDim.x*blockDim.x;
    for (int j=i;j<48;j+=st) d_e[j]=0.f;
    for (int j=i;j<NN;j+=st){ d_deg_r[j]=0; d_deg_s[j]=0; }
}

// ---- fused edge geometry + degree histogram ---------------------------------
__global__ void k_geom_hist(const float* __restrict__ pos, const float* __restrict__ shifts,
                            const int* __restrict__ ei){
    int e = blockIdx.x*blockDim.x + threadIdx.x;
    if (e >= NE) return;
    int s = ei[e], t = ei[NE+e];
    atomicAdd(&d_deg_r[t],1);
    atomicAdd(&d_deg_s[s],1);
    float vx = pos[t*3+0]-pos[s*3+0]+shifts[e*3+0];
    float vy = pos[t*3+1]-pos[s*3+1]+shifts[e*3+1];
    float vz = pos[t*3+2]-pos[s*3+2]+shifts[e*3+2];
    float r  = sqrtf(vx*vx+vy*vy+vz*vz + 1e-12f);
    d_vec[e*3+0]=vx; d_vec[e*3+1]=vy; d_vec[e*3+2]=vz; d_r[e]=r;
    float inv = 1.0f/r;
    float x=vx*inv, y=vy*inv, z=vz*inv;
    d_Y[e*8+0]=S3f*y;  d_Y[e*8+1]=S3f*z;  d_Y[e*8+2]=S3f*x;
    d_Y[e*8+3]=S15f*x*y; d_Y[e*8+4]=S15f*y*z;
    d_Y[e*8+5]=0.5f*S5f*(3.f*z*z-1.f);
    d_Y[e*8+6]=S15f*x*z; d_Y[e*8+7]=0.5f*S15f*(x*x-y*y);
}

__global__ void k_scan(){
    __shared__ int sh[1024];
    int t = threadIdx.x;
    for (int w=0; w<2; w++){
        int* deg = w? d_deg_s: d_deg_r;
        int* off = w? d_off_s: d_off_r;
        int* cur = w? d_cur_s: d_cur_r;
        int base = t*10, s=0;
        #pragma unroll
        for (int i=0;i<10;i++){ int idx=base+i; if (idx<NN) s+=deg[idx]; }
        sh[t]=s;
        __syncthreads();
        for (int d=1; d<1024; d<<=1){
            int v = (t>=d)? sh[t-d]:0;
            __syncthreads();
            sh[t]+=v;
            __syncthreads();
        }
        int run = sh[t]-s;
        #pragma unroll
        for (int i=0;i<10;i++){ int idx=base+i; if (idx<NN){ off[idx]=run; cur[idx]=run; run+=deg[idx]; } }
        if (t==0) off[NN]=NE;
        __syncthreads();
    }
}

__global__ void k_csr_fill(const int* __restrict__ ei){
    int e = blockIdx.x*blockDim.x + threadIdx.x;
    int p = atomicAdd(&d_cur_r[ei[NE+e]],1); d_csr_r[p]=e;
    int q = atomicAdd(&d_cur_s[ei[e]],1);    d_csr_s[q]=e;
}

// ----------------------------------------------------------------------------
__global__ void k_precW(const float* __restrict__ w_out0, const float* __restrict__ w_up1){
    int c = blockIdx.x, l = blockIdx.y+1, d2 = threadIdx.x;
    const float* wo = w_out0 + l*4096;
    const float* wu = w_up1  + l*4096;
    float a=0.f;
    for (int d=0;d<64;d++) a = fmaf(wo[c*64+d], wu[d*64+d2], a);
    if (l==1) d_W01[c*64+d2]=a; else d_W02[c*64+d2]=a;
}

// ------------------------- LUT build: dual-number MLP (K-baked) --------------
#define MM64(DST,SRC) do{ \
    _Pragma("unroll") for(int i=0;i<8;i++) DST[i]=0.f; \
    _Pragma("unroll") for(int k0=0;k0<64;k0+=4){ \
        _Pragma("unroll") for(int i=0;i<8;i++){ \
            float4 a4=*(const float4*)&SRC[r0+i][k0]; \
            DST[i]=fmaf(a4.x,wc[k0],DST[i]); DST[i]=fmaf(a4.y,wc[k0+1],DST[i]); \
            DST[i]=fmaf(a4.z,wc[k0+2],DST[i]); DST[i]=fmaf(a4.w,wc[k0+3],DST[i]); } } \
}while(0)
#define FILLW() _Pragma("unroll") for(int k=0;k<64;k++) wc[k]=sW[k*65+j]

__global__ void __launch_bounds__(256) k_lut_build(const float* __restrict__ w1,
        const float* __restrict__ w2, const float* __restrict__ w3,
        const float* __restrict__ w4, int w4s, int cb1, int cb2, int which,
        float kp0, float kp1, float kp2){
    __shared__ float sV[32][64];
    __shared__ float sT[32][64];
    __shared__ float sW[64*65];
    int tid=threadIdx.x, j=tid&63, r0=(tid>>6)*8;
    int row0=blockIdx.x*32;
    float* LR = which? d_lutR1 : d_lutR0;
    float* LD = which? d_lutD1 : d_lutD0;
    {
        int rr=tid>>3, q=tid&7;
        float rv = (float)(row0+rr)*LUT_H;
        float rs = fmaxf(rv, 1e-6f);
        float inv = 1.0f/rs;
        float uu = rs*0.2f;
        float u2=uu*uu, u4=u2*u2, u5=u4*uu, u6=u5*uu, u7=u6*uu;
        float fc  = 1.f - 21.f*u5 + 35.f*u6 - 15.f*u7;
        float dfc = (-105.f*u4 + 210.f*u5 - 105.f*u6)*0.2f;
        if (uu >= 1.0f){ fc=0.f; dfc=0.f; }
        float a = (float)(q+1)*(PIf/5.0f);
        float sa=sinf(a*rs), ca=cosf(a*rs);
        float c0 = sqrtf(0.4f);
        sV[rr][q] = c0*sa*inv*fc;
        sT[rr][q] = c0*((a*ca*inv - sa*inv*inv)*fc + sa*inv*dfc);
    }
    __syncthreads();
    float aV[8], aT[8], wc[64];
    #pragma unroll
    for (int i=0;i<8;i++){ aV[i]=0.f; aT[i]=0.f; }
    #pragma unroll
    for (int k=0;k<8;k++){
        float w=w1[k*64+j];
        #pragma unroll
        for (int i=0;i<8;i++){ aV[i]=fmaf(sV[r0+i][k],w,aV[i]); aT[i]=fmaf(sT[r0+i][k],w,aT[i]); }
    }
    __syncthreads();
    #pragma unroll
    for (int i=0;i<8;i++){ float z=aV[i]; sV[r0+i][j]=siluf(z); sT[r0+i][j]=dsiluf(z)*aT[i]; }
    for(int idx=tid; idx<4096; idx+=256){ int a_=idx>>6, b_=idx&63; sW[a_*65+b_]=w2[idx]; }
    __syncthreads();
    FILLW();
    MM64(aV, sV);
    MM64(aT, sT);
    __syncthreads();
    #pragma unroll
    for (int i=0;i<8;i++){ float z=aV[i]; sV[r0+i][j]=siluf(z); sT[r0+i][j]=dsiluf(z)*aT[i]; }
    for(int idx=tid; idx<4096; idx+=256){ int a_=idx>>6, b_=idx&63; sW[a_*65+b_]=w3[idx]; }
    __syncthreads();
    FILLW();
    MM64(aV, sV);
    MM64(aT, sT);
    __syncthreads();
    #pragma unroll
    for (int i=0;i<8;i++){ float z=aV[i]; sV[r0+i][j]=siluf(z); sT[r0+i][j]=dsiluf(z)*aT[i]; }
    int cbs[3]={0,cb1,cb2};
    float kps[3]={kp0,kp1,kp2};
    for (int p=0;p<3;p++){
        for(int idx=tid; idx<4096; idx+=256){ int a_=idx>>6, b_=idx&63; sW[a_*65+b_]=w4[a_*w4s+cbs[p]+b_]; }
        __syncthreads();
        FILLW();
        MM64(aV, sV);
        MM64(aT, sT);
        float kp = kps[p];
        #pragma unroll
        for (int i=0;i<8;i++){
            LR[(row0+r0+i)*192 + p*64 + j] = kp*aV[i];
            LD[(row0+r0+i)*192 + p*64 + j] = kp*aT[i];
        }
        __syncthreads();
    }
}

// ----------------------------------------------------------------------------
__global__ void k_node_init(const float* __restrict__ attrs, const float* __restrict__ w_emb,
                            const float* __restrict__ w_up0, const float* __restrict__ aener,
                            const int* __restrict__ batch){
    int n = blockIdx.x, c = threadIdx.x;
    __shared__ int ssp;
    __shared__ float sh0[64];
    if (c==0){
        int sp=0;
        for (int q=0;q<10;q++) if (attrs[n*10+q] > 0.5f) sp=q;
        ssp=sp; d_sp[n]=sp;
        atomicAdd(&d_e[batch[n]], aener[sp]);
    }
    __syncthreads();
    sh0[c]=w_emb[ssp*64+c];
    __syncthreads();
    float a=0.f;
    for (int k=0;k<64;k++) a = fmaf(sh0[k], w_up0[k*64+c], a);
    d_hup0[n*64+c]=a;
}

// ------------------ interaction 0: fused agg + node mix ----------------------
__global__ void k_int0(const int* __restrict__ ei, const float* __restrict__ w_emb,
                       const float* __restrict__ w_out0, const float* __restrict__ w_sc0,
                       const float* __restrict__ w_r0, const float* __restrict__ w_up1,
                       const int* __restrict__ batch){
    int n=blockIdx.x, tx=threadIdx.x;
    __shared__ float sA0[64], sA1[192], sA2[320], sh0[64], sh1[64];
    __shared__ float sred[2];
    int sp = d_sp[n];
    float a0=0.f, a1[3]={0,0,0}, a2[5]={0,0,0,0,0};
    int b0=d_off_r[n], b1=d_off_r[n+1];
    for (int q=b0;q<b1;q++){
        int e=d_csr_r[q]; int s=ei[e];
        int li; float w; lut_idx(d_r[e], li, w);
        const float* A = d_lutR0 + li*192;
        float hup=d_hup0[s*64+tx];
        const float* Ye=d_Y+e*8;
        a0 = fmaf(hup, lerpf(A, tx, w), a0);
        float m1 = hup*lerpf(A, 64+tx, w);
        #pragma unroll
        for (int i=0;i<3;i++) a1[i]=fmaf(m1,Ye[i],a1[i]);
        float m2 = hup*lerpf(A, 128+tx, w);
        #pragma unroll
        for (int i=0;i<5;i++) a2[i]=fmaf(m2,Ye[3+i],a2[i]);
    }
    sA0[tx]=a0;
    #pragma unroll
    for (int i=0;i<3;i++) sA1[i*64+tx]=a1[i];
    #pragma unroll
    for (int i=0;i<5;i++) sA2[i*64+tx]=a2[i];
    sh0[tx]=w_emb[sp*64+tx];
    __syncthreads();
    const float* wsc = w_sc0 + sp*4096;
    float acc=0.f;
    for (int c=0;c<64;c++){
        acc = fmaf(sA0[c], w_out0[c*64+tx], acc);
        acc = fmaf(sh0[c], wsc[c*64+tx], acc);
    }
    d_h1_0[n*64+tx]=acc;
    sh1[tx]=acc;
    float ev = acc*w_r0[tx];
    #pragma unroll
    for (int off=16;off>0;off>>=1) ev += __shfl_xor_sync(0xffffffffu, ev, off);
    if ((tx&31)==0) sred[tx>>5]=ev;
    __syncthreads();
    if (tx==0) atomicAdd(&d_e[16+batch[n]], sred[0]+sred[1]);
    float a=0.f;
    for (int c=0;c<64;c++) a = fmaf(sh1[c], w_up1[c*64+tx], a);
    d_hup1_0[n*64+tx]=a;
    float bb[3]={0,0,0};
    for (int c=0;c<64;c++){
        float w = d_W01[c*64+tx];
        #pragma unroll
        for (int i=0;i<3;i++) bb[i]=fmaf(sA1[i*64+c],w,bb[i]);
    }
    #pragma unroll
    for (int i=0;i<3;i++) d_hup1_1[i*N64+n*64+tx]=bb[i];
    float ee[5]={0,0,0,0,0};
    for (int c=0;c<64;c++){
        float w = d_W02[c*64+tx];
        #pragma unroll
        for (int i=0;i<5;i++) ee[i]=fmaf(sA2[i*64+c],w,ee[i]);
    }
    #pragma unroll
    for (int i=0;i<5;i++) d_hup1_2[i*N64+n*64+tx]=ee[i];
}

// ------------------ interaction 1: fused agg + node mix ----------------------
__global__ void k_int1(const int* __restrict__ ei, const float* __restrict__ w_out1,
                       const float* __restrict__ w_sc1, const float* __restrict__ w_m1,
                       const float* __restrict__ w_m2, const float* __restrict__ w_r0,
                       const int* __restrict__ batch){
    int n=blockIdx.x, tx=threadIdx.x;
    __shared__ float sA0[64], sA1[64], sA2[64], sh1[64], sh2[64], sg2[64];
    __shared__ float sv[16], sdz[16];
    int sp=d_sp[n];
    float a0=0.f, a1=0.f, a2=0.f;
    int b0=d_off_r[n], b1=d_off_r[n+1];
    for (int q=b0;q<b1;q++){
        int e=d_csr_r[q]; int s=ei[e];
        int li; float w; lut_idx(d_r[e], li, w);
        const float* A = d_lutR1 + li*192;
        const float* Ye=d_Y+e*8;
        a0 = fmaf(d_hup1_0[s*64+tx], lerpf(A, tx, w), a0);
        float S1=0.f;
        #pragma unroll
        for (int i=0;i<3;i++) S1 = fmaf(Ye[i], d_hup1_1[i*N64+s*64+tx], S1);
        a1 = fmaf(S1, lerpf(A, 64+tx, w), a1);
        float S2=0.f;
        #pragma unroll
        for (int i=0;i<5;i++) S2 = fmaf(Ye[3+i], d_hup1_2[i*N64+s*64+tx], S2);
        a2 = fmaf(S2, lerpf(A, 128+tx, w), a2);
    }
    sA0[tx]=a0; sA1[tx]=a1; sA2[tx]=a2;
    sh1[tx]=d_h1_0[n*64+tx];
    __syncthreads();
    const float* wo0 = w_out1;
    const float* wo4 = w_out1 + 4*4096;
    const float* wo9 = w_out1 + 9*4096;
    const float* wsc = w_sc1 + sp*4096;
    float h2=0.f;
    for (int c=0;c<64;c++){
        h2 = fmaf(sA0[c], wo0[c*64+tx], h2);
        h2 = fmaf(sA1[c], wo4[c*64+tx], h2);
        h2 = fmaf(sA2[c], wo9[c*64+tx], h2);
        h2 = fmaf(sh1[c], wsc[c*64+tx], h2);
    }
    sh2[tx]=h2;
    __syncthreads();
    if (tx < 16){
        float z=0.f;
        for (int d=0;d<64;d++) z = fmaf(sh2[d], w_m1[d*16+tx], z);
        float s=1.f/(1.f+expf(-z));
        sv[tx]  = z*s*w_m2[tx];
        sdz[tx] = s*(1.f+z*(1.f-s))*w_m2[tx];
    }
    __syncthreads();
    if (tx==0){
        float t=0.f;
        for (int q=0;q<16;q++) t+=sv[q];
        atomicAdd(&d_e[32+batch[n]], t);
    }
    float gh2=0.f;
    #pragma unroll
    for (int q=0;q<16;q++) gh2 = fmaf(w_m1[tx*16+q], sdz[q], gh2);
    sg2[tx]=gh2;
    __syncthreads();
    float ga0=0.f, ga1=0.f, ga2=0.f, gh1=w_r0[tx];
    for (int d=0;d<64;d++){
        float g = sg2[d];
        ga0 = fmaf(wo0[tx*64+d], g, ga0);
        ga1 = fmaf(wo4[tx*64+d], g, ga1);
        ga2 = fmaf(wo9[tx*64+d], g, ga2);
        gh1 = fmaf(wsc[tx*64+d], g, gh1);
    }
    d_gagg1[n*64+tx]=ga0;
    d_gagg1[N64+n*64+tx]=ga1;
    d_gagg1[2*N64+n*64+tx]=ga2;
    d_gh1_0[n*64+tx]=gh1;
}

// --------------- int1 backward: fused sender-gather + node mix ---------------
__global__ void k_int1_bwd(const int* __restrict__ ei, const float* __restrict__ w_up1,
                           const float* __restrict__ w_out0){
    int n=blockIdx.x, tx=threadIdx.x;
    __shared__ float sg0[64], sgh1[64], sg1[192], sg2[320];
    float g0a=0.f, g1a[3]={0,0,0}, g2a[5]={0,0,0,0,0};
    int b0=d_off_s[n], b1=d_off_s[n+1];
    for (int q=b0;q<b1;q++){
        int e=d_csr_s[q]; int t=ei[NE+e];
        int li; float w; lut_idx(d_r[e], li, w);
        const float* A = d_lutR1 + li*192;
        const float* Ye=d_Y+e*8;
        float g0=d_gagg1[t*64+tx];
        float g1=d_gagg1[N64+t*64+tx];
        float g2=d_gagg1[2*N64+t*64+tx];
        g0a = fmaf(lerpf(A, tx, w), g0, g0a);
        float aa1 = lerpf(A, 64+tx, w)*g1;
        #pragma unroll
        for (int i=0;i<3;i++) g1a[i]=fmaf(aa1,Ye[i],g1a[i]);
        float aa2 = lerpf(A, 128+tx, w)*g2;
        #pragma unroll
        for (int i=0;i<5;i++) g2a[i]=fmaf(aa2,Ye[3+i],g2a[i]);
    }
    sg0[tx]=g0a;
    #pragma unroll
    for (int i=0;i<3;i++) sg1[i*64+tx]=g1a[i];
    #pragma unroll
    for (int i=0;i<5;i++) sg2[i*64+tx]=g2a[i];
    __syncthreads();
    float gh1 = d_gh1_0[n*64+tx];
    for (int d=0;d<64;d++) gh1 = fmaf(sg0[d], w_up1[tx*64+d], gh1);
    sgh1[tx]=gh1;
    __syncthreads();
    float ga=0.f;
    for (int d=0;d<64;d++) ga = fmaf(w_out0[tx*64+d], sgh1[d], ga);
    d_gagg0_0[n*64+tx]=ga;
    float bb[3]={0,0,0};
    for (int d=0;d<64;d++){
        float w = d_W01[tx*64+d];
        #pragma unroll
        for (int i=0;i<3;i++) bb[i]=fmaf(sg1[i*64+d],w,bb[i]);
    }
    #pragma unroll
    for (int i=0;i<3;i++) d_gagg0_1[i*N64+n*64+tx]=bb[i];
    float cc[5]={0,0,0,0,0};
    for (int d=0;d<64;d++){
        float w = d_W02[tx*64+d];
        #pragma unroll
        for (int i=0;i<5;i++) cc[i]=fmaf(sg2[i*64+d],w,cc[i]);
    }
    #pragma unroll
    for (int i=0;i<5;i++) d_gagg0_2[i*N64+n*64+tx]=cc[i];
}

// --------- FUSED backward edge pass: both layers -> gvec directly ------------
__global__ void k_bwd_edge(const int* __restrict__ ei){
    int gtid = blockIdx.x*blockDim.x + threadIdx.x;
    int e = gtid>>5, lane = gtid&31;
    int s = ei[e], t = ei[NE+e];
    float r = d_r[e];
    int li; float w; lut_idx(r, li, w);
    const float* A1 = d_lutR1 + li*192;
    const float* D1 = d_lutD1 + li*192;
    const float* A0 = d_lutR0 + li*192;
    const float* D0 = d_lutD0 + li*192;
    float y[8];
    #pragma unroll
    for (int i=0;i<8;i++) y[i]=d_Y[e*8+i];
    float tY[8]={0,0,0,0,0,0,0,0};
    float gr=0.f;
    #pragma unroll
    for (int h=0;h<2;h++){
        int c = lane + 32*h;
        // ---- layer 1 backward ----
        {
            float g0 = d_gagg1[t*64+c];
            float g1 = d_gagg1[N64+t*64+c];
            float g2 = d_gagg1[2*N64+t*64+c];
            float h0v = d_hup1_0[s*64+c];
            float h1v[3], h2v[5];
            #pragma unroll
            for (int i=0;i<3;i++) h1v[i]=d_hup1_1[i*N64+s*64+c];
            #pragma unroll
            for (int i=0;i<5;i++) h2v[i]=d_hup1_2[i*N64+s*64+c];
            float s1 = y[0]*h1v[0]+y[1]*h1v[1]+y[2]*h1v[2];
            float s2 = y[3]*h2v[0]+y[4]*h2v[1]+y[5]*h2v[2]+y[6]*h2v[3]+y[7]*h2v[4];
            gr = fmaf(lerpf(D1, c, w),      h0v*g0, gr);
            gr = fmaf(lerpf(D1, 64+c, w),   s1*g1,  gr);
            gr = fmaf(lerpf(D1, 128+c, w),  s2*g2,  gr);
            float a1 = lerpf(A1, 64+c, w)*g1;
            float a2 = lerpf(A1, 128+c, w)*g2;
            #pragma unroll
            for (int i=0;i<3;i++) tY[i]   = fmaf(a1,h1v[i],tY[i]);
            #pragma unroll
            for (int i=0;i<5;i++) tY[3+i] = fmaf(a2,h2v[i],tY[3+i]);
        }
        // ---- layer 0 backward ----
        {
            float hp = d_hup0[s*64+c];
            float ga0 = d_gagg0_0[t*64+c];
            float ga1[3], ga2[5];
            #pragma unroll
            for (int i=0;i<3;i++) ga1[i]=d_gagg0_1[i*N64+t*64+c];
            #pragma unroll
            for (int i=0;i<5;i++) ga2[i]=d_gagg0_2[i*N64+t*64+c];
            float s1 = y[0]*ga1[0]+y[1]*ga1[1]+y[2]*ga1[2];
            float s2 = y[3]*ga2[0]+y[4]*ga2[1]+y[5]*ga2[2]+y[6]*ga2[3]+y[7]*ga2[4];
            gr = fmaf(lerpf(D0, c, w),     hp*ga0, gr);
            gr = fmaf(lerpf(D0, 64+c, w),  hp*s1,  gr);
            gr = fmaf(lerpf(D0, 128+c, w), hp*s2,  gr);
            float b1 = lerpf(A0, 64+c, w)*hp;
            float b2 = lerpf(A0, 128+c, w)*hp;
            #pragma unroll
            for (int i=0;i<3;i++) tY[i]   = fmaf(b1, ga1[i], tY[i]);
            #pragma unroll
            for (int i=0;i<5;i++) tY[3+i] = fmaf(b2, ga2[i], tY[3+i]);
        }
    }
    #pragma unroll
    for (int i=0;i<8;i++){
        float v=tY[i];
        #pragma unroll
        for (int off=16;off>0;off>>=1) v += __shfl_xor_sync(0xffffffffu, v, off);
        tY[i]=v;
    }
    #pragma unroll
    for (int off=16;off>0;off>>=1) gr += __shfl_xor_sync(0xffffffffu, gr, off);
    if (lane==0){
        float vx=d_vec[e*3+0], vy=d_vec[e*3+1], vz=d_vec[e*3+2];
        float inv = 1.0f/r;
        float x=vx*inv, yv=vy*inv, z=vz*inv;
        float gux = S3f*tY[2] + S15f*(yv*tY[3] + z*tY[6] + x*tY[7]);
        float guy = S3f*tY[0] + S15f*(x*tY[3] + z*tY[4] - yv*tY[7]);
        float guz = S3f*tY[1] + S15f*(yv*tY[4] + x*tY[6]) + 3.f*S5f*z*tY[5];
        float dot = x*gux + yv*guy + z*guz;
        d_gvec[e*3+0] = (gux - x*dot)*inv + gr*x;
        d_gvec[e*3+1] = (guy - yv*dot)*inv + gr*yv;
        d_gvec[e*3+2] = (guz - z*dot)*inv + gr*z;
    }
}

// ----------------------------------------------------------------------------
__global__ void k_force_node(float* __restrict__ out){
    int n = blockIdx.x*4 + (threadIdx.x>>5);
    int lane = threadIdx.x&31;
    float fx=0.f, fy=0.f, fz=0.f;
    int b0=d_off_r[n], b1=d_off_r[n+1];
    for (int q=b0+lane;q<b1;q+=32){
        int e=d_csr_r[q];
        fx-=d_gvec[e*3+0]; fy-=d_gvec[e*3+1]; fz-=d_gvec[e*3+2];
    }
    b0=d_off_s[n]; b1=d_off_s[n+1];
    for (int q=b0+lane;q<b1;q+=32){
        int e=d_csr_s[q];
        fx+=d_gvec[e*3+0]; fy+=d_gvec[e*3+1]; fz+=d_gvec[e*3+2];
    }
    #pragma unroll
    for (int off=16;off>0;off>>=1){
        fx+=__shfl_xor_sync(0xffffffffu,fx,off);
        fy+=__shfl_xor_sync(0xffffffffu,fy,off);
        fz+=__shfl_xor_sync(0xffffffffu,fz,off);
    }
    if (lane==0){
        float* F = out + 64;
        F[n*3+0]=fx; F[n*3+1]=fy; F[n*3+2]=fz;
    }
}

// ----------------------------------------------------------------------------
__global__ void k_finalize(float* __restrict__ out){
    int g = threadIdx.x;
    if (g >= 16) return;
    float e0=d_e[g], e1=d_e[16+g], e2=d_e[32+g];
    out[g] = e0+e1+e2;
    out[16+g*3+0]=e0; out[16+g*3+1]=e1; out[16+g*3+2]=e2;
}

// ----------------------------------------------------------------------------
extern "C" void kernel_launch(void* const* d_in, const int* in_sizes, int n_in,
                              void* d_out, int out_size){
    const float* pos    = (const float*)d_in[0];
    const float* attrs  = (const float*)d_in[1];
    const float* shifts = (const float*)d_in[2];
    const float* aener  = (const float*)d_in[3];
    const float* w_emb  = (const float*)d_in[4];
    const float* w_up0  = (const float*)d_in[5];
    const float* r0w1   = (const float*)d_in[6];
    const float* r0w2   = (const float*)d_in[7];
    const float* r0w3   = (const float*)d_in[8];
    const float* r0w4   = (const float*)d_in[9];
    const float* w_out0 = (const float*)d_in[10];
    const float* w_sc0  = (const float*)d_in[11];
    const float* w_r0   = (const float*)d_in[12];
    const float* w_up1  = (const float*)d_in[13];
    const float* r1w1   = (const float*)d_in[14];
    const float* r1w2   = (const float*)d_in[15];
    const float* r1w3   = (const float*)d_in[16];
    const float* r1w4   = (const float*)d_in[17];
    const float* w_out1 = (const float*)d_in[18];
    const float* w_sc1  = (const float*)d_in[19];
    const float* w_m1   = (const float*)d_in[20];
    const float* w_m2   = (const float*)d_in[21];
    const int*   ei     = (const int*)d_in[22];
    const int*   batch  = (const int*)d_in[23];
    float* out = (float*)d_out;

    k_zero<<<64,256>>>();
    k_geom_hist<<<625,256>>>(pos, shifts, ei);
    k_scan<<<1,1024>>>();
    k_csr_fill<<<625,256>>>(ei);
    k_precW<<<dim3(64,2),64>>>(w_out0, w_up1);
    k_lut_build<<<NLUT/32,256>>>(r0w1,r0w2,r0w3,r0w4, 192, 64, 128, 0, K0C, K1C, K2C);
    k_lut_build<<<NLUT/32,256>>>(r1w1,r1w2,r1w3,r1w4, 832, 256, 576, 1, K0C, K4N, K9N);
    k_node_init<<<NN,64>>>(attrs, w_emb, w_up0, aener, batch);
    k_int0<<<NN,64>>>(ei, w_emb, w_out0, w_sc0, w_r0, w_up1, batch);
    k_int1<<<NN,64>>>(ei, w_out1, w_sc1, w_m1, w_m2, w_r0, batch);
    k_int1_bwd<<<NN,64>>>(ei, w_up1, w_out0);
    k_bwd_edge<<<NE*32/256,256>>>(ei);
    k_force_node<<<NN/4,128>>>(out);
    k_finalize<<<1,16>>>(out);
}